// round 6
// baseline (speedup 1.0000x reference)
#include <cuda_runtime.h>
#include <cuda_bf16.h>
#include <math.h>
#include <stdint.h>

// ---------------- problem constants ----------------
#define BB 4
#define QQ 600
#define LL 2048
#define DD 256
#define HH 8
#define HD 32
#define DFF 2048
#define KD 32
#define SCALE 0.17677669529663687f   // 32^-0.5
#define NQT 10                       // ceil(600/64) 64-query tiles

typedef unsigned long long u64;

// ---------------- helpers ----------------
__device__ __forceinline__ uint32_t f2tf32(float x) {
    uint32_t u; asm("cvt.rna.tf32.f32 %0, %1;" : "=r"(u) : "f"(x)); return u;
}
__device__ __forceinline__ void mma8(float c[4], uint32_t a0, uint32_t a1,
                                     uint32_t a2, uint32_t a3,
                                     uint32_t b0, uint32_t b1) {
    asm("mma.sync.aligned.m16n8k8.row.col.f32.tf32.tf32.f32 "
        "{%0,%1,%2,%3},{%4,%5,%6,%7},{%8,%9},{%0,%1,%2,%3};"
        : "+f"(c[0]), "+f"(c[1]), "+f"(c[2]), "+f"(c[3])
        : "r"(a0), "r"(a1), "r"(a2), "r"(a3), "r"(b0), "r"(b1));
}
__device__ __forceinline__ void cp16(uint32_t dst, const void* src, int srcsize) {
    asm volatile("cp.async.ca.shared.global [%0], [%1], 16, %2;"
                 :: "r"(dst), "l"(src), "r"(srcsize));
}
__device__ __forceinline__ void cp_commit() {
    asm volatile("cp.async.commit_group;");
}
template<int N>
__device__ __forceinline__ void cp_wait() {
    asm volatile("cp.async.wait_group %0;" :: "n"(N));
}

// ---------------- scratch (device globals) ----------------
__device__ float s_qkv [BB*QQ*3*DD];
__device__ float s_sa  [BB*QQ*DD];
__device__ float s_tmp [BB*QQ*DD];
__device__ float s_x1  [BB*QQ*DD];
__device__ float s_x2  [BB*QQ*DD];
__device__ float s_q   [BB*QQ*DD];
__device__ float s_k   [BB*LL*DD];
__device__ float s_v   [BB*LL*DD];
__device__ float s_bias[BB*LL*QQ];           // beta * clipped bias, [B, L, Q]
__device__ float s_ca  [BB*QQ*DD];
__device__ float s_ffn [BB*QQ*DFF];
__device__ float s_part[4*BB*QQ*DD];         // ffn2 split-K partials
__device__ float s_pm  [BB*HH*8*QQ];
__device__ float s_pl  [BB*HH*8*QQ];
__device__ float s_pacc[BB*HH*8*QQ*HD];

// ---------------- TF32 tensor-core GEMM (3-stage cp.async pipeline) -------
// C[M,N] = A[M,K] @ W[N,K]^T (+bias, opt relu). 256 threads, 8 warps (4m x 2n).
// MF = m-frags per warp (1 -> BM=64, 2 -> BM=128).
// grid.z = split-K count: if >1, each z writes a bias-free partial.
// DUAL: if W2 != nullptr, blockIdx.x >= N/64 uses W2/bias2/C2 (fused 2nd GEMM
// sharing the same A — e.g. K-proj + V-proj).
#define KPAD 20
#define NST 3

template<int MF>
__global__ __launch_bounds__(256) void gemm_tf32_kernel(
    const float* __restrict__ A, const float* __restrict__ W,
    const float* __restrict__ bias, float* __restrict__ C,
    int M, int N, int K, int relu,
    const float* __restrict__ W2 = nullptr,
    const float* __restrict__ bias2 = nullptr,
    float* __restrict__ C2 = nullptr)
{
    __shared__ __align__(16) uint32_t As[NST][64 * MF][KPAD];
    __shared__ __align__(16) uint32_t Ws[NST][64][KPAD];

    const int tid = threadIdx.x;
    const int lane = tid & 31;
    const int w = tid >> 5;
    const int wm = w & 3;
    const int wn = w >> 2;
    const int g = lane >> 2;
    const int t = lane & 3;

    int bx = blockIdx.x;
    const int nblk = N / 64;
    if (W2 != nullptr && bx >= nblk) {
        bx -= nblk;
        W = W2; bias = bias2; C = C2;
    }

    const int m0 = blockIdx.y * (64 * MF);
    const int n0 = bx * 64;

    const int nsplit = gridDim.z;
    const int Klen = K / nsplit;
    const int kstart = blockIdx.z * Klen;
    float* Cout = (nsplit > 1) ? (C + (size_t)blockIdx.z * M * N) : C;

    const int lr = tid >> 2;
    const int kc = (tid & 3) * 4;

    const uint32_t as_base = (uint32_t)__cvta_generic_to_shared(&As[0][0][0]);
    const uint32_t ws_base = (uint32_t)__cvta_generic_to_shared(&Ws[0][0][0]);

    float acc[MF][4][4];
    #pragma unroll
    for (int i = 0; i < MF; i++)
        #pragma unroll
        for (int j = 0; j < 4; j++)
            #pragma unroll
            for (int e = 0; e < 4; e++) acc[i][j][e] = 0.f;

    const int m_warp = wm * (16 * MF);
    const int n_warp = wn * 32;
    const int nIter = Klen / 16;

    auto load_stage = [&](int st, int it) {
        const int kg = kstart + it * 16 + kc;
        #pragma unroll
        for (int half = 0; half < MF; half++) {
            int r = lr + half * 64;
            int arow = m0 + r;
            uint32_t dst = as_base + ((st * (64 * MF) + r) * KPAD + kc) * 4;
            const float* src = A + (size_t)arow * K + kg;
            cp16(dst, src, (arow < M) ? 16 : 0);
        }
        {
            uint32_t dst = ws_base + ((st * 64 + lr) * KPAD + kc) * 4;
            const float* src = W + (size_t)(n0 + lr) * K + kg;
            cp16(dst, src, 16);
        }
        cp_commit();
    };

    // prologue: stages 0..NST-2
    load_stage(0, 0);
    load_stage(1, 1);

    for (int it = 0; it < nIter; it++) {
        cp_wait<NST - 2>();            // stage it%NST landed
        __syncthreads();               // all warps done reading stage (it-1)%NST
        if (it + NST - 1 < nIter) load_stage((it + NST - 1) % NST, it + NST - 1);
        else cp_commit();              // keep group arithmetic aligned

        const int st = it % NST;
        #pragma unroll
        for (int kk = 0; kk < 16; kk += 8) {
            uint32_t b0[4], b1[4];
            #pragma unroll
            for (int ni = 0; ni < 4; ni++) {
                b0[ni] = Ws[st][n_warp + ni * 8 + g][kk + t];
                b1[ni] = Ws[st][n_warp + ni * 8 + g][kk + t + 4];
            }
            #pragma unroll
            for (int mi = 0; mi < MF; mi++) {
                int mb = m_warp + mi * 16;
                uint32_t a0 = As[st][mb + g][kk + t];
                uint32_t a1 = As[st][mb + g + 8][kk + t];
                uint32_t a2 = As[st][mb + g][kk + t + 4];
                uint32_t a3 = As[st][mb + g + 8][kk + t + 4];
                #pragma unroll
                for (int ni = 0; ni < 4; ni++)
                    mma8(acc[mi][ni], a0, a1, a2, a3, b0[ni], b1[ni]);
            }
        }
    }

    #pragma unroll
    for (int mi = 0; mi < MF; mi++) {
        #pragma unroll
        for (int ni = 0; ni < 4; ni++) {
            int col = n0 + n_warp + ni * 8 + 2 * t;
            float bz0 = 0.f, bz1 = 0.f;
            if (nsplit == 1) { bz0 = bias[col]; bz1 = bias[col + 1]; }
            int r0 = m0 + m_warp + mi * 16 + g;
            int r1 = r0 + 8;
            float v0 = acc[mi][ni][0] + bz0, v1 = acc[mi][ni][1] + bz1;
            float v2 = acc[mi][ni][2] + bz0, v3 = acc[mi][ni][3] + bz1;
            if (relu) {
                v0 = fmaxf(v0, 0.f); v1 = fmaxf(v1, 0.f);
                v2 = fmaxf(v2, 0.f); v3 = fmaxf(v3, 0.f);
            }
            if (r0 < M) *reinterpret_cast<float2*>(Cout + (size_t)r0 * N + col) = make_float2(v0, v1);
            if (r1 < M) *reinterpret_cast<float2*>(Cout + (size_t)r1 * N + col) = make_float2(v2, v3);
        }
    }
}

// ---------------- LayerNorm helpers ----------------
__device__ __forceinline__ void ln_core(float v, int tid, const float* g,
                                        const float* bt, float* out, size_t row)
{
    float s1 = v, s2 = v * v;
    #pragma unroll
    for (int o = 16; o > 0; o >>= 1) {
        s1 += __shfl_xor_sync(0xffffffffu, s1, o);
        s2 += __shfl_xor_sync(0xffffffffu, s2, o);
    }
    __shared__ float r1[8], r2[8];
    int wid = tid >> 5, lane = tid & 31;
    if (lane == 0) { r1[wid] = s1; r2[wid] = s2; }
    __syncthreads();
    if (tid < 32) {
        float a = (lane < 8) ? r1[lane] : 0.f;
        float b = (lane < 8) ? r2[lane] : 0.f;
        #pragma unroll
        for (int o = 4; o > 0; o >>= 1) {
            a += __shfl_xor_sync(0xffffffffu, a, o);
            b += __shfl_xor_sync(0xffffffffu, b, o);
        }
        if (lane == 0) { r1[0] = a; r2[0] = b; }
    }
    __syncthreads();
    float mean = r1[0] * (1.f / DD);
    float var = r2[0] * (1.f / DD) - mean * mean;
    out[row * DD + tid] = (v - mean) * rsqrtf(var + 1e-5f) * g[tid] + bt[tid];
}

__global__ __launch_bounds__(256) void ln_kernel(
    const float* __restrict__ A, const float* __restrict__ R,
    const float* __restrict__ g, const float* __restrict__ bt,
    float* __restrict__ out)
{
    const size_t row = blockIdx.x;
    const int tid = threadIdx.x;
    float v = A[row * DD + tid] + R[row * DD + tid];
    ln_core(v, tid, g, bt, out, row);
}

__global__ __launch_bounds__(256) void ln_split_kernel(
    const float* __restrict__ X, const float* __restrict__ parts,
    const float* __restrict__ fbias,
    const float* __restrict__ g, const float* __restrict__ bt,
    float* __restrict__ out, int nsplit)
{
    const size_t row = blockIdx.x;
    const int tid = threadIdx.x;
    const size_t stride = (size_t)BB * QQ * DD;
    float f = fbias[tid];
    for (int s = 0; s < nsplit; s++) f += parts[s * stride + row * DD + tid];
    float v = X[row * DD + tid] + f;
    ln_core(v, tid, g, bt, out, row);
}

// ---------------- GASA geometric bias: block per (b,l), 128 thr x 5 q -----
__global__ __launch_bounds__(128) void gasa_bias_kernel(
    const float* __restrict__ qpos, const float* __restrict__ mpos,
    const float* __restrict__ w1, const float* __restrict__ b1,
    const float* __restrict__ w2, const float* __restrict__ b2,
    const float* __restrict__ betap, float* __restrict__ biasT)
{
    const int l = blockIdx.x;
    const int b = blockIdx.y;
    const int tid = threadIdx.x;

    __shared__ float sw1[KD], sb1[KD], sw2[KD], smp[3], sb2, sbeta;
    if (tid < KD) {
        sw1[tid] = w1[tid];
        sb1[tid] = b1[tid];
        sw2[tid] = w2[tid];
    }
    if (tid < 3) smp[tid] = mpos[((size_t)b * LL + l) * 3 + tid];
    if (tid == 3) sb2 = b2[0];
    if (tid == 4) sbeta = betap[0];
    __syncthreads();

    const float mx = smp[0], my = smp[1], mz = smp[2];
    const float bb2 = sb2, bet = sbeta;
    float* orow = biasT + ((size_t)b * LL + l) * QQ;

    for (int q = tid; q < QQ; q += 128) {
        const float* qp = qpos + ((size_t)b * QQ + q) * 3;
        float dx = qp[0] - mx, dy = qp[1] - my, dz = qp[2] - mz;
        float dist = sqrtf(fmaxf(dx * dx + dy * dy + dz * dz, 0.f));
        float s = 0.f;
        #pragma unroll
        for (int k = 0; k < KD; k++) {
            float h = fmaxf(dist * sw1[k] + sb1[k], 0.f);
            s += h * sw2[k];
        }
        s += bb2;
        s = fminf(fmaxf(s, -10.f), 0.f);
        orow[q] = s * bet;
    }
}

// ---------------- tensor-core flash attention partials ----------------
// Block: 128 threads = 4 warps; warp owns 16 queries; block = 64 queries.
// Chunk: 16 keys. Scores & PV on mma.m16n8k8.tf32.
__global__ __launch_bounds__(128) void attn_mma_kernel(
    const float* __restrict__ Qp, int qstride,
    const float* __restrict__ Kp, const float* __restrict__ Vp, int kvstride,
    const float* __restrict__ biasT, int Lk, int S, int step,
    float* __restrict__ pm, float* __restrict__ pl, float* __restrict__ pacc,
    int useBias)
{
    const int b = blockIdx.z, h = blockIdx.y;
    const int sp = blockIdx.x / NQT;
    const int qt = blockIdx.x % NQT;
    const int tid = threadIdx.x;
    const int lane = tid & 31;
    const int warp = tid >> 5;
    const int g = lane >> 2;
    const int t = lane & 3;

    const int q0 = qt * 64 + warp * 16;
    const int qg  = q0 + g;
    const int qg8 = q0 + g + 8;
    const int qgc  = min(qg, QQ - 1);
    const int qg8c = min(qg8, QQ - 1);

    const int ls = sp * step;
    const int le = min(ls + step, Lk);

    uint32_t qa[4][4];
    {
        const float* q0p = Qp + ((size_t)(b * QQ + qgc)) * qstride + h * HD;
        const float* q1p = Qp + ((size_t)(b * QQ + qg8c)) * qstride + h * HD;
        #pragma unroll
        for (int ks = 0; ks < 4; ks++) {
            qa[ks][0] = f2tf32(q0p[ks * 8 + t] * SCALE);
            qa[ks][1] = f2tf32(q1p[ks * 8 + t] * SCALE);
            qa[ks][2] = f2tf32(q0p[ks * 8 + t + 4] * SCALE);
            qa[ks][3] = f2tf32(q1p[ks * 8 + t + 4] * SCALE);
        }
    }

    __shared__ uint32_t Ks[16][36];
    __shared__ uint32_t Vt[HD][17];

    float oacc[4][4];
    #pragma unroll
    for (int i = 0; i < 4; i++)
        #pragma unroll
        for (int j = 0; j < 4; j++) oacc[i][j] = 0.f;
    float om0 = -INFINITY, om1 = -INFINITY;
    float ol0 = 0.f, ol1 = 0.f;

    const int key_l = tid >> 3;
    const int d0 = (tid & 7) * 4;

    for (int l0 = ls; l0 < le; l0 += 16) {
        {
            int grow = b * Lk + min(l0 + key_l, Lk - 1);
            float4 kv = *reinterpret_cast<const float4*>(
                Kp + (size_t)grow * kvstride + h * HD + d0);
            uint4 ku = make_uint4(f2tf32(kv.x), f2tf32(kv.y), f2tf32(kv.z), f2tf32(kv.w));
            *reinterpret_cast<uint4*>(&Ks[key_l][d0]) = ku;
            float4 vv = *reinterpret_cast<const float4*>(
                Vp + (size_t)grow * kvstride + h * HD + d0);
            Vt[d0 + 0][key_l] = f2tf32(vv.x);
            Vt[d0 + 1][key_l] = f2tf32(vv.y);
            Vt[d0 + 2][key_l] = f2tf32(vv.z);
            Vt[d0 + 3][key_l] = f2tf32(vv.w);
        }
        __syncthreads();

        float sc[2][4];
        #pragma unroll
        for (int nf = 0; nf < 2; nf++) {
            sc[nf][0] = sc[nf][1] = sc[nf][2] = sc[nf][3] = 0.f;
            #pragma unroll
            for (int ks = 0; ks < 4; ks++) {
                uint32_t b0 = Ks[nf * 8 + g][ks * 8 + t];
                uint32_t b1 = Ks[nf * 8 + g][ks * 8 + t + 4];
                mma8(sc[nf], qa[ks][0], qa[ks][1], qa[ks][2], qa[ks][3], b0, b1);
            }
        }

        #pragma unroll
        for (int nf = 0; nf < 2; nf++) {
            int kc = l0 + nf * 8 + 2 * t;
            if (useBias) {
                const float* bp0 = biasT + ((size_t)(b * Lk + min(kc, Lk - 1))) * QQ;
                const float* bp1 = biasT + ((size_t)(b * Lk + min(kc + 1, Lk - 1))) * QQ;
                sc[nf][0] += bp0[qgc];
                sc[nf][1] += bp1[qgc];
                sc[nf][2] += bp0[qg8c];
                sc[nf][3] += bp1[qg8c];
            }
            if (kc >= le)     { sc[nf][0] = -1e30f; sc[nf][2] = -1e30f; }
            if (kc + 1 >= le) { sc[nf][1] = -1e30f; sc[nf][3] = -1e30f; }
        }

        float mx0 = fmaxf(fmaxf(sc[0][0], sc[0][1]), fmaxf(sc[1][0], sc[1][1]));
        float mx1 = fmaxf(fmaxf(sc[0][2], sc[0][3]), fmaxf(sc[1][2], sc[1][3]));
        mx0 = fmaxf(mx0, __shfl_xor_sync(0xffffffffu, mx0, 1));
        mx0 = fmaxf(mx0, __shfl_xor_sync(0xffffffffu, mx0, 2));
        mx1 = fmaxf(mx1, __shfl_xor_sync(0xffffffffu, mx1, 1));
        mx1 = fmaxf(mx1, __shfl_xor_sync(0xffffffffu, mx1, 2));

        float nm0 = fmaxf(om0, mx0), nm1 = fmaxf(om1, mx1);
        float cr0 = __expf(om0 - nm0), cr1 = __expf(om1 - nm1);
        om0 = nm0; om1 = nm1;
        ol0 *= cr0; ol1 *= cr1;
        #pragma unroll
        for (int nd = 0; nd < 4; nd++) {
            oacc[nd][0] *= cr0; oacc[nd][1] *= cr0;
            oacc[nd][2] *= cr1; oacc[nd][3] *= cr1;
        }

        #pragma unroll
        for (int nf = 0; nf < 2; nf++) {
            sc[nf][0] = __expf(sc[nf][0] - nm0);
            sc[nf][1] = __expf(sc[nf][1] - nm0);
            sc[nf][2] = __expf(sc[nf][2] - nm1);
            sc[nf][3] = __expf(sc[nf][3] - nm1);
            ol0 += sc[nf][0] + sc[nf][1];
            ol1 += sc[nf][2] + sc[nf][3];
        }

        #pragma unroll
        for (int ks = 0; ks < 2; ks++) {
            int src0 = t >> 1, src1 = (t >> 1) + 2;
            float v0 = __shfl_sync(0xffffffffu, sc[ks][0], src0, 4);
            float v1 = __shfl_sync(0xffffffffu, sc[ks][1], src0, 4);
            float v2 = __shfl_sync(0xffffffffu, sc[ks][2], src0, 4);
            float v3 = __shfl_sync(0xffffffffu, sc[ks][3], src0, 4);
            float w0 = __shfl_sync(0xffffffffu, sc[ks][0], src1, 4);
            float w1 = __shfl_sync(0xffffffffu, sc[ks][1], src1, 4);
            float w2 = __shfl_sync(0xffffffffu, sc[ks][2], src1, 4);
            float w3 = __shfl_sync(0xffffffffu, sc[ks][3], src1, 4);
            bool odd = (t & 1);
            uint32_t pa0 = f2tf32(odd ? v1 : v0);
            uint32_t pa1 = f2tf32(odd ? v3 : v2);
            uint32_t pa2 = f2tf32(odd ? w1 : w0);
            uint32_t pa3 = f2tf32(odd ? w3 : w2);
            #pragma unroll
            for (int nd = 0; nd < 4; nd++) {
                uint32_t b0 = Vt[nd * 8 + g][ks * 8 + t];
                uint32_t b1 = Vt[nd * 8 + g][ks * 8 + t + 4];
                mma8(oacc[nd], pa0, pa1, pa2, pa3, b0, b1);
            }
        }
        __syncthreads();
    }

    ol0 += __shfl_xor_sync(0xffffffffu, ol0, 1);
    ol0 += __shfl_xor_sync(0xffffffffu, ol0, 2);
    ol1 += __shfl_xor_sync(0xffffffffu, ol1, 1);
    ol1 += __shfl_xor_sync(0xffffffffu, ol1, 2);

    size_t pbase = ((size_t)((b * HH + h) * S + sp)) * QQ;
    if (qg < QQ) {
        if (t == 0) { pm[pbase + qg] = om0; pl[pbase + qg] = ol0; }
        float* ap = pacc + (pbase + qg) * HD;
        #pragma unroll
        for (int nd = 0; nd < 4; nd++)
            *reinterpret_cast<float2*>(ap + nd * 8 + 2 * t) =
                make_float2(oacc[nd][0], oacc[nd][1]);
    }
    if (qg8 < QQ) {
        if (t == 0) { pm[pbase + qg8] = om1; pl[pbase + qg8] = ol1; }
        float* ap = pacc + (pbase + qg8) * HD;
        #pragma unroll
        for (int nd = 0; nd < 4; nd++)
            *reinterpret_cast<float2*>(ap + nd * 8 + 2 * t) =
                make_float2(oacc[nd][2], oacc[nd][3]);
    }
}

// ---------------- split combine (parallel over d-pairs) ----------------
__global__ __launch_bounds__(256) void attn_combine_kernel(
    const float* __restrict__ pm, const float* __restrict__ pl,
    const float* __restrict__ pacc, int S, float* __restrict__ out)
{
    int tt = blockIdx.x * 256 + threadIdx.x;
    if (tt >= BB * HH * QQ * (HD / 2)) return;
    int dp = tt & (HD / 2 - 1);
    int idx = tt >> 4;
    int q = idx % QQ;
    int bh = idx / QQ;
    int b = bh / HH, h = bh % HH;

    float mg = -INFINITY;
    for (int s = 0; s < S; s++)
        mg = fmaxf(mg, pm[((size_t)bh * S + s) * QQ + q]);
    float Lsum = 0.f;
    float olo = 0.f, ohi = 0.f;
    for (int s = 0; s < S; s++) {
        size_t pidx = ((size_t)bh * S + s) * QQ + q;
        float w = __expf(pm[pidx] - mg);
        Lsum += pl[pidx] * w;
        float2 a = *reinterpret_cast<const float2*>(pacc + pidx * HD + 2 * dp);
        olo += w * a.x; ohi += w * a.y;
    }
    float inv = 1.f / Lsum;
    float2* op = reinterpret_cast<float2*>(
        out + ((size_t)(b * QQ + q)) * DD + h * HD + 2 * dp);
    *op = make_float2(olo * inv, ohi * inv);
}

// ---------------- host launcher ----------------
static inline int cdiv(int a, int b) { return (a + b - 1) / b; }

extern "C" void kernel_launch(void* const* d_in, const int* in_sizes, int n_in,
                              void* d_out, int out_size)
{
    const float* queries   = (const float*)d_in[0];
    const float* memory    = (const float*)d_in[1];
    const float* memory_pos= (const float*)d_in[2];
    const float* query_pos = (const float*)d_in[3];
    const float* sa_in_w   = (const float*)d_in[4];
    const float* sa_in_b   = (const float*)d_in[5];
    const float* sa_out_w  = (const float*)d_in[6];
    const float* sa_out_b  = (const float*)d_in[7];
    const float* norm1_g   = (const float*)d_in[8];
    const float* norm1_b   = (const float*)d_in[9];
    const float* q_w       = (const float*)d_in[10];
    const float* q_b       = (const float*)d_in[11];
    const float* k_w       = (const float*)d_in[12];
    const float* k_b       = (const float*)d_in[13];
    const float* v_w       = (const float*)d_in[14];
    const float* v_b       = (const float*)d_in[15];
    const float* o_w       = (const float*)d_in[16];
    const float* o_b       = (const float*)d_in[17];
    const float* norm2_g   = (const float*)d_in[18];
    const float* norm2_b   = (const float*)d_in[19];
    const float* beta      = (const float*)d_in[20];
    const float* dk_w1     = (const float*)d_in[21];
    const float* dk_b1     = (const float*)d_in[22];
    const float* dk_w2     = (const float*)d_in[23];
    const float* dk_b2     = (const float*)d_in[24];
    const float* ffn_w1    = (const float*)d_in[25];
    const float* ffn_b1    = (const float*)d_in[26];
    const float* ffn_w2    = (const float*)d_in[27];
    const float* ffn_b2    = (const float*)d_in[28];
    const float* norm3_g   = (const float*)d_in[29];
    const float* norm3_b   = (const float*)d_in[30];

    float *g_qkv, *g_sa, *g_tmp, *g_x1, *g_x2, *g_q, *g_k, *g_v, *g_bias,
          *g_ca, *g_ffn, *g_part, *g_pm, *g_pl, *g_pacc;
    cudaGetSymbolAddress((void**)&g_qkv,  s_qkv);
    cudaGetSymbolAddress((void**)&g_sa,   s_sa);
    cudaGetSymbolAddress((void**)&g_tmp,  s_tmp);
    cudaGetSymbolAddress((void**)&g_x1,   s_x1);
    cudaGetSymbolAddress((void**)&g_x2,   s_x2);
    cudaGetSymbolAddress((void**)&g_q,    s_q);
    cudaGetSymbolAddress((void**)&g_k,    s_k);
    cudaGetSymbolAddress((void**)&g_v,    s_v);
    cudaGetSymbolAddress((void**)&g_bias, s_bias);
    cudaGetSymbolAddress((void**)&g_ca,   s_ca);
    cudaGetSymbolAddress((void**)&g_ffn,  s_ffn);
    cudaGetSymbolAddress((void**)&g_part, s_part);
    cudaGetSymbolAddress((void**)&g_pm,   s_pm);
    cudaGetSymbolAddress((void**)&g_pl,   s_pl);
    cudaGetSymbolAddress((void**)&g_pacc, s_pacc);

    const int Mq = BB * QQ;   // 2400
    const int Mm = BB * LL;   // 8192
    const int NCOMB = BB * HH * QQ * (HD / 2);

    // 1) self-attn packed in-proj [2400,768]
    gemm_tf32_kernel<2><<<dim3(3 * DD / 64, cdiv(Mq, 128), 1), 256>>>(
        queries, sa_in_w, sa_in_b, g_qkv, Mq, 3 * DD, DD, 0);

    // GASA geometric bias (independent — launch early)
    gasa_bias_kernel<<<dim3(LL, BB), 128>>>(
        query_pos, memory_pos, dk_w1, dk_b1, dk_w2, dk_b2, beta, g_bias);

    // K-proj + V-proj fused (A shared)
    gemm_tf32_kernel<2><<<dim3(2 * DD / 64, cdiv(Mm, 128), 1), 256>>>(
        memory, k_w, k_b, g_k, Mm, DD, DD, 0, v_w, v_b, g_v);

    // 2) self-attention (no bias), split S=2
    {
        int S = 2, step = cdiv(QQ, S * 16) * 16;   // 304
        attn_mma_kernel<<<dim3(NQT * S, HH, BB), 128>>>(
            g_qkv, 3 * DD, g_qkv + DD, g_qkv + 2 * DD, 3 * DD,
            nullptr, QQ, S, step, g_pm, g_pl, g_pacc, 0);
        attn_combine_kernel<<<cdiv(NCOMB, 256), 256>>>(g_pm, g_pl, g_pacc, S, g_sa);
    }

    // 3) SA out-proj + LN1
    gemm_tf32_kernel<1><<<dim3(DD / 64, cdiv(Mq, 64), 1), 256>>>(
        g_sa, sa_out_w, sa_out_b, g_tmp, Mq, DD, DD, 0);
    ln_kernel<<<Mq, 256>>>(queries, g_tmp, norm1_g, norm1_b, g_x1);

    // 4) Q projection
    gemm_tf32_kernel<1><<<dim3(DD / 64, cdiv(Mq, 64), 1), 256>>>(
        g_x1, q_w, q_b, g_q, Mq, DD, DD, 0);

    // 5) cross-attention with bias, split S=2 (step 1024)
    {
        int S = 2, step = cdiv(LL, S * 16) * 16;   // 1024
        attn_mma_kernel<<<dim3(NQT * S, HH, BB), 128>>>(
            g_q, DD, g_k, g_v, DD, g_bias, LL, S, step, g_pm, g_pl, g_pacc, 1);
        attn_combine_kernel<<<cdiv(NCOMB, 256), 256>>>(g_pm, g_pl, g_pacc, S, g_ca);
    }

    // 6) O proj + LN2
    gemm_tf32_kernel<1><<<dim3(DD / 64, cdiv(Mq, 64), 1), 256>>>(
        g_ca, o_w, o_b, g_tmp, Mq, DD, DD, 0);
    ln_kernel<<<Mq, 256>>>(g_x1, g_tmp, norm2_g, norm2_b, g_x2);

    // 7) FFN1 (relu)
    gemm_tf32_kernel<2><<<dim3(DFF / 64, cdiv(Mq, 128), 1), 256>>>(
        g_x2, ffn_w1, ffn_b1, g_ffn, Mq, DFF, DD, 1);

    // 8) FFN2 split-K=4 partials + fused combine in LN3 -> output
    gemm_tf32_kernel<1><<<dim3(DD / 64, cdiv(Mq, 64), 4), 256>>>(
        g_ffn, ffn_w2, ffn_b2, g_part, Mq, DD, DFF, 0);
    ln_split_kernel<<<Mq, 256>>>(g_x2, g_part, ffn_b2, norm3_g, norm3_b,
                                 (float*)d_out, 4);
}

// round 7
// speedup vs baseline: 1.1657x; 1.1657x over previous
#include <cuda_runtime.h>
#include <cuda_bf16.h>
#include <math.h>
#include <stdint.h>

// ---------------- problem constants ----------------
#define BB 4
#define QQ 600
#define LL 2048
#define DD 256
#define HH 8
#define HD 32
#define DFF 2048
#define KD 32
#define SCALE 0.17677669529663687f   // 32^-0.5
#define NQT 10                       // ceil(600/64) 64-query tiles

typedef unsigned long long u64;

// ---------------- helpers ----------------
__device__ __forceinline__ uint32_t f2tf32(float x) {
    uint32_t u; asm("cvt.rna.tf32.f32 %0, %1;" : "=r"(u) : "f"(x)); return u;
}
__device__ __forceinline__ void mma8(float c[4], uint32_t a0, uint32_t a1,
                                     uint32_t a2, uint32_t a3,
                                     uint32_t b0, uint32_t b1) {
    asm("mma.sync.aligned.m16n8k8.row.col.f32.tf32.tf32.f32 "
        "{%0,%1,%2,%3},{%4,%5,%6,%7},{%8,%9},{%0,%1,%2,%3};"
        : "+f"(c[0]), "+f"(c[1]), "+f"(c[2]), "+f"(c[3])
        : "r"(a0), "r"(a1), "r"(a2), "r"(a3), "r"(b0), "r"(b1));
}
__device__ __forceinline__ void cp16(uint32_t dst, const void* src, int srcsize) {
    asm volatile("cp.async.ca.shared.global [%0], [%1], 16, %2;"
                 :: "r"(dst), "l"(src), "r"(srcsize));
}
__device__ __forceinline__ void cp_commit() {
    asm volatile("cp.async.commit_group;");
}
template<int N>
__device__ __forceinline__ void cp_wait() {
    asm volatile("cp.async.wait_group %0;" :: "n"(N));
}

// ---------------- scratch (device globals) ----------------
__device__ float s_qkv [BB*QQ*3*DD];
__device__ float s_sa  [BB*QQ*DD];
__device__ float s_tmp [BB*QQ*DD];
__device__ float s_x1  [BB*QQ*DD];
__device__ float s_x2  [BB*QQ*DD];
__device__ float s_q   [BB*QQ*DD];
__device__ float s_k   [BB*LL*DD];
__device__ float s_v   [BB*LL*DD];
__device__ float s_bias[BB*LL*QQ];           // beta * clipped bias, [B, L, Q]
__device__ float s_ca  [BB*QQ*DD];
__device__ float s_ffn [BB*QQ*DFF];
__device__ float s_part[4*BB*QQ*DD];         // ffn2 split-K partials
__device__ float s_pm  [BB*HH*8*QQ];
__device__ float s_pl  [BB*HH*8*QQ];
__device__ float s_pacc[BB*HH*8*QQ*HD];

// ---------------- TF32 tensor-core GEMM (3-stage cp.async pipeline) -------
#define KPAD 20
#define NST 3

template<int MF>
__global__ __launch_bounds__(256) void gemm_tf32_kernel(
    const float* __restrict__ A, const float* __restrict__ W,
    const float* __restrict__ bias, float* __restrict__ C,
    int M, int N, int K, int relu,
    const float* __restrict__ W2 = nullptr,
    const float* __restrict__ bias2 = nullptr,
    float* __restrict__ C2 = nullptr)
{
    __shared__ __align__(16) uint32_t As[NST][64 * MF][KPAD];
    __shared__ __align__(16) uint32_t Ws[NST][64][KPAD];

    const int tid = threadIdx.x;
    const int lane = tid & 31;
    const int w = tid >> 5;
    const int wm = w & 3;
    const int wn = w >> 2;
    const int g = lane >> 2;
    const int t = lane & 3;

    int bx = blockIdx.x;
    const int nblk = N / 64;
    if (W2 != nullptr && bx >= nblk) {
        bx -= nblk;
        W = W2; bias = bias2; C = C2;
    }

    const int m0 = blockIdx.y * (64 * MF);
    const int n0 = bx * 64;

    const int nsplit = gridDim.z;
    const int Klen = K / nsplit;
    const int kstart = blockIdx.z * Klen;
    float* Cout = (nsplit > 1) ? (C + (size_t)blockIdx.z * M * N) : C;

    const int lr = tid >> 2;
    const int kc = (tid & 3) * 4;

    const uint32_t as_base = (uint32_t)__cvta_generic_to_shared(&As[0][0][0]);
    const uint32_t ws_base = (uint32_t)__cvta_generic_to_shared(&Ws[0][0][0]);

    float acc[MF][4][4];
    #pragma unroll
    for (int i = 0; i < MF; i++)
        #pragma unroll
        for (int j = 0; j < 4; j++)
            #pragma unroll
            for (int e = 0; e < 4; e++) acc[i][j][e] = 0.f;

    const int m_warp = wm * (16 * MF);
    const int n_warp = wn * 32;
    const int nIter = Klen / 16;

    auto load_stage = [&](int st, int it) {
        const int kg = kstart + it * 16 + kc;
        #pragma unroll
        for (int half = 0; half < MF; half++) {
            int r = lr + half * 64;
            int arow = m0 + r;
            uint32_t dst = as_base + ((st * (64 * MF) + r) * KPAD + kc) * 4;
            const float* src = A + (size_t)arow * K + kg;
            cp16(dst, src, (arow < M) ? 16 : 0);
        }
        {
            uint32_t dst = ws_base + ((st * 64 + lr) * KPAD + kc) * 4;
            const float* src = W + (size_t)(n0 + lr) * K + kg;
            cp16(dst, src, 16);
        }
        cp_commit();
    };

    load_stage(0, 0);
    load_stage(1, 1);

    for (int it = 0; it < nIter; it++) {
        cp_wait<NST - 2>();
        __syncthreads();
        if (it + NST - 1 < nIter) load_stage((it + NST - 1) % NST, it + NST - 1);
        else cp_commit();

        const int st = it % NST;
        #pragma unroll
        for (int kk = 0; kk < 16; kk += 8) {
            uint32_t b0[4], b1[4];
            #pragma unroll
            for (int ni = 0; ni < 4; ni++) {
                b0[ni] = Ws[st][n_warp + ni * 8 + g][kk + t];
                b1[ni] = Ws[st][n_warp + ni * 8 + g][kk + t + 4];
            }
            #pragma unroll
            for (int mi = 0; mi < MF; mi++) {
                int mb = m_warp + mi * 16;
                uint32_t a0 = As[st][mb + g][kk + t];
                uint32_t a1 = As[st][mb + g + 8][kk + t];
                uint32_t a2 = As[st][mb + g][kk + t + 4];
                uint32_t a3 = As[st][mb + g + 8][kk + t + 4];
                #pragma unroll
                for (int ni = 0; ni < 4; ni++)
                    mma8(acc[mi][ni], a0, a1, a2, a3, b0[ni], b1[ni]);
            }
        }
    }

    #pragma unroll
    for (int mi = 0; mi < MF; mi++) {
        #pragma unroll
        for (int ni = 0; ni < 4; ni++) {
            int col = n0 + n_warp + ni * 8 + 2 * t;
            float bz0 = 0.f, bz1 = 0.f;
            if (nsplit == 1) { bz0 = bias[col]; bz1 = bias[col + 1]; }
            int r0 = m0 + m_warp + mi * 16 + g;
            int r1 = r0 + 8;
            float v0 = acc[mi][ni][0] + bz0, v1 = acc[mi][ni][1] + bz1;
            float v2 = acc[mi][ni][2] + bz0, v3 = acc[mi][ni][3] + bz1;
            if (relu) {
                v0 = fmaxf(v0, 0.f); v1 = fmaxf(v1, 0.f);
                v2 = fmaxf(v2, 0.f); v3 = fmaxf(v3, 0.f);
            }
            if (r0 < M) *reinterpret_cast<float2*>(Cout + (size_t)r0 * N + col) = make_float2(v0, v1);
            if (r1 < M) *reinterpret_cast<float2*>(Cout + (size_t)r1 * N + col) = make_float2(v2, v3);
        }
    }
}

// ---------------- LayerNorm helpers ----------------
__device__ __forceinline__ void ln_core(float v, int tid, const float* g,
                                        const float* bt, float* out, size_t row)
{
    float s1 = v, s2 = v * v;
    #pragma unroll
    for (int o = 16; o > 0; o >>= 1) {
        s1 += __shfl_xor_sync(0xffffffffu, s1, o);
        s2 += __shfl_xor_sync(0xffffffffu, s2, o);
    }
    __shared__ float r1[8], r2[8];
    int wid = tid >> 5, lane = tid & 31;
    if (lane == 0) { r1[wid] = s1; r2[wid] = s2; }
    __syncthreads();
    if (tid < 32) {
        float a = (lane < 8) ? r1[lane] : 0.f;
        float b = (lane < 8) ? r2[lane] : 0.f;
        #pragma unroll
        for (int o = 4; o > 0; o >>= 1) {
            a += __shfl_xor_sync(0xffffffffu, a, o);
            b += __shfl_xor_sync(0xffffffffu, b, o);
        }
        if (lane == 0) { r1[0] = a; r2[0] = b; }
    }
    __syncthreads();
    float mean = r1[0] * (1.f / DD);
    float var = r2[0] * (1.f / DD) - mean * mean;
    out[row * DD + tid] = (v - mean) * rsqrtf(var + 1e-5f) * g[tid] + bt[tid];
}

__global__ __launch_bounds__(256) void ln_kernel(
    const float* __restrict__ A, const float* __restrict__ R,
    const float* __restrict__ g, const float* __restrict__ bt,
    float* __restrict__ out)
{
    const size_t row = blockIdx.x;
    const int tid = threadIdx.x;
    float v = A[row * DD + tid] + R[row * DD + tid];
    ln_core(v, tid, g, bt, out, row);
}

__global__ __launch_bounds__(256) void ln_split_kernel(
    const float* __restrict__ X, const float* __restrict__ parts,
    const float* __restrict__ fbias,
    const float* __restrict__ g, const float* __restrict__ bt,
    float* __restrict__ out, int nsplit)
{
    const size_t row = blockIdx.x;
    const int tid = threadIdx.x;
    const size_t stride = (size_t)BB * QQ * DD;
    float f = fbias[tid];
    for (int s = 0; s < nsplit; s++) f += parts[s * stride + row * DD + tid];
    float v = X[row * DD + tid] + f;
    ln_core(v, tid, g, bt, out, row);
}

// ---------------- GASA geometric bias: block per (b,l) ----------------
__global__ __launch_bounds__(128) void gasa_bias_kernel(
    const float* __restrict__ qpos, const float* __restrict__ mpos,
    const float* __restrict__ w1, const float* __restrict__ b1,
    const float* __restrict__ w2, const float* __restrict__ b2,
    const float* __restrict__ betap, float* __restrict__ biasT)
{
    const int l = blockIdx.x;
    const int b = blockIdx.y;
    const int tid = threadIdx.x;

    __shared__ float sw1[KD], sb1[KD], sw2[KD], smp[3], sb2, sbeta;
    if (tid < KD) {
        sw1[tid] = w1[tid];
        sb1[tid] = b1[tid];
        sw2[tid] = w2[tid];
    }
    if (tid < 3) smp[tid] = mpos[((size_t)b * LL + l) * 3 + tid];
    if (tid == 3) sb2 = b2[0];
    if (tid == 4) sbeta = betap[0];
    __syncthreads();

    const float mx = smp[0], my = smp[1], mz = smp[2];
    const float bb2 = sb2, bet = sbeta;
    float* orow = biasT + ((size_t)b * LL + l) * QQ;

    for (int q = tid; q < QQ; q += 128) {
        const float* qp = qpos + ((size_t)b * QQ + q) * 3;
        float dx = qp[0] - mx, dy = qp[1] - my, dz = qp[2] - mz;
        float dist = sqrtf(fmaxf(dx * dx + dy * dy + dz * dz, 0.f));
        float s = 0.f;
        #pragma unroll
        for (int k = 0; k < KD; k++) {
            float h = fmaxf(dist * sw1[k] + sb1[k], 0.f);
            s += h * sw2[k];
        }
        s += bb2;
        s = fminf(fmaxf(s, -10.f), 0.f);
        orow[q] = s * bet;
    }
}

// ---------------- tensor-core flash attention partials ----------------
// Block: 128 threads = 4 warps; warp owns 16 queries; block = 64 queries.
// Chunk: 16 keys. Register-prefetch of next chunk (K/V/bias) overlaps LDG
// latency with current-chunk compute; bias staged via smem (coalesced).
__global__ __launch_bounds__(128) void attn_mma_kernel(
    const float* __restrict__ Qp, int qstride,
    const float* __restrict__ Kp, const float* __restrict__ Vp, int kvstride,
    const float* __restrict__ biasT, int Lk, int S, int step,
    float* __restrict__ pm, float* __restrict__ pl, float* __restrict__ pacc,
    int useBias)
{
    const int b = blockIdx.z, h = blockIdx.y;
    const int sp = blockIdx.x / NQT;
    const int qt = blockIdx.x % NQT;
    const int tid = threadIdx.x;
    const int lane = tid & 31;
    const int warp = tid >> 5;
    const int g = lane >> 2;
    const int t = lane & 3;

    const int q0 = qt * 64 + warp * 16;
    const int qg  = q0 + g;
    const int qg8 = q0 + g + 8;
    const int qgc  = min(qg, QQ - 1);
    const int qg8c = min(qg8, QQ - 1);

    const int ls = sp * step;
    const int le = min(ls + step, Lk);

    uint32_t qa[4][4];
    {
        const float* q0p = Qp + ((size_t)(b * QQ + qgc)) * qstride + h * HD;
        const float* q1p = Qp + ((size_t)(b * QQ + qg8c)) * qstride + h * HD;
        #pragma unroll
        for (int ks = 0; ks < 4; ks++) {
            qa[ks][0] = f2tf32(q0p[ks * 8 + t] * SCALE);
            qa[ks][1] = f2tf32(q1p[ks * 8 + t] * SCALE);
            qa[ks][2] = f2tf32(q0p[ks * 8 + t + 4] * SCALE);
            qa[ks][3] = f2tf32(q1p[ks * 8 + t + 4] * SCALE);
        }
    }

    __shared__ uint32_t Ks[16][36];      // [key][d]   (36*4=144B rows, 16B mult)
    __shared__ uint32_t Vt[HD][17];      // [d][key]
    __shared__ float    Bsm[16][68];     // [key][qlocal] (68*4=272B rows, 16B mult)

    float oacc[4][4];
    #pragma unroll
    for (int i = 0; i < 4; i++)
        #pragma unroll
        for (int j = 0; j < 4; j++) oacc[i][j] = 0.f;
    float om0 = -INFINITY, om1 = -INFINITY;
    float ol0 = 0.f, ol1 = 0.f;

    const int key_l = tid >> 3;          // 0..15
    const int d0 = (tid & 7) * 4;        // 0..28
    const int bq0 = (tid & 7) * 8;       // bias col base 0..56
    const bool qtail = (qt == NQT - 1);

    float4 kreg, vreg, breg0, breg1;

    // prefetch: chunk at l0 -> registers
    auto prefetch = [&](int l0) {
        int grow = b * Lk + min(l0 + key_l, Lk - 1);
        kreg = *reinterpret_cast<const float4*>(
            Kp + (size_t)grow * kvstride + h * HD + d0);
        vreg = *reinterpret_cast<const float4*>(
            Vp + (size_t)grow * kvstride + h * HD + d0);
        if (useBias) {
            const float* brow = biasT + ((size_t)(b * Lk + l0 + key_l)) * QQ
                                + qt * 64 + bq0;
            if (!qtail) {
                breg0 = *reinterpret_cast<const float4*>(brow);
                breg1 = *reinterpret_cast<const float4*>(brow + 4);
            } else {
                int qb = qt * 64 + bq0;
                float e[8];
                #pragma unroll
                for (int i = 0; i < 8; i++)
                    e[i] = (qb + i < QQ) ? brow[i] : 0.f;
                breg0 = make_float4(e[0], e[1], e[2], e[3]);
                breg1 = make_float4(e[4], e[5], e[6], e[7]);
            }
        }
    };

    prefetch(ls);

    for (int l0 = ls; l0 < le; l0 += 16) {
        __syncthreads();                 // prior compute done reading smem
        // stage registers -> smem (tf32 convert K/V here)
        {
            uint4 ku = make_uint4(f2tf32(kreg.x), f2tf32(kreg.y),
                                  f2tf32(kreg.z), f2tf32(kreg.w));
            *reinterpret_cast<uint4*>(&Ks[key_l][d0]) = ku;
            Vt[d0 + 0][key_l] = f2tf32(vreg.x);
            Vt[d0 + 1][key_l] = f2tf32(vreg.y);
            Vt[d0 + 2][key_l] = f2tf32(vreg.z);
            Vt[d0 + 3][key_l] = f2tf32(vreg.w);
            if (useBias) {
                *reinterpret_cast<float4*>(&Bsm[key_l][bq0]) = breg0;
                *reinterpret_cast<float4*>(&Bsm[key_l][bq0 + 4]) = breg1;
            }
        }
        if (l0 + 16 < le) prefetch(l0 + 16);
        __syncthreads();

        // --- scores ---
        float sc[2][4];
        #pragma unroll
        for (int nf = 0; nf < 2; nf++) {
            sc[nf][0] = sc[nf][1] = sc[nf][2] = sc[nf][3] = 0.f;
            #pragma unroll
            for (int ks = 0; ks < 4; ks++) {
                uint32_t b0 = Ks[nf * 8 + g][ks * 8 + t];
                uint32_t b1 = Ks[nf * 8 + g][ks * 8 + t + 4];
                mma8(sc[nf], qa[ks][0], qa[ks][1], qa[ks][2], qa[ks][3], b0, b1);
            }
        }

        // --- bias (smem) + key-bound mask ---
        #pragma unroll
        for (int nf = 0; nf < 2; nf++) {
            if (useBias) {
                int brow = nf * 8 + 2 * t;
                int c0 = warp * 16 + g;
                sc[nf][0] += Bsm[brow][c0];
                sc[nf][1] += Bsm[brow + 1][c0];
                sc[nf][2] += Bsm[brow][c0 + 8];
                sc[nf][3] += Bsm[brow + 1][c0 + 8];
            }
            int kc = l0 + nf * 8 + 2 * t;
            if (kc >= le)     { sc[nf][0] = -1e30f; sc[nf][2] = -1e30f; }
            if (kc + 1 >= le) { sc[nf][1] = -1e30f; sc[nf][3] = -1e30f; }
        }

        // --- row max + online rescale ---
        float mx0 = fmaxf(fmaxf(sc[0][0], sc[0][1]), fmaxf(sc[1][0], sc[1][1]));
        float mx1 = fmaxf(fmaxf(sc[0][2], sc[0][3]), fmaxf(sc[1][2], sc[1][3]));
        mx0 = fmaxf(mx0, __shfl_xor_sync(0xffffffffu, mx0, 1));
        mx0 = fmaxf(mx0, __shfl_xor_sync(0xffffffffu, mx0, 2));
        mx1 = fmaxf(mx1, __shfl_xor_sync(0xffffffffu, mx1, 1));
        mx1 = fmaxf(mx1, __shfl_xor_sync(0xffffffffu, mx1, 2));

        float nm0 = fmaxf(om0, mx0), nm1 = fmaxf(om1, mx1);
        float cr0 = __expf(om0 - nm0), cr1 = __expf(om1 - nm1);
        om0 = nm0; om1 = nm1;
        ol0 *= cr0; ol1 *= cr1;
        #pragma unroll
        for (int nd = 0; nd < 4; nd++) {
            oacc[nd][0] *= cr0; oacc[nd][1] *= cr0;
            oacc[nd][2] *= cr1; oacc[nd][3] *= cr1;
        }

        // --- P = exp(S - m) ---
        #pragma unroll
        for (int nf = 0; nf < 2; nf++) {
            sc[nf][0] = __expf(sc[nf][0] - nm0);
            sc[nf][1] = __expf(sc[nf][1] - nm0);
            sc[nf][2] = __expf(sc[nf][2] - nm1);
            sc[nf][3] = __expf(sc[nf][3] - nm1);
            ol0 += sc[nf][0] + sc[nf][1];
            ol1 += sc[nf][2] + sc[nf][3];
        }

        // --- P transpose + PV mma ---
        #pragma unroll
        for (int ks = 0; ks < 2; ks++) {
            int src0 = t >> 1, src1 = (t >> 1) + 2;
            float v0 = __shfl_sync(0xffffffffu, sc[ks][0], src0, 4);
            float v1 = __shfl_sync(0xffffffffu, sc[ks][1], src0, 4);
            float v2 = __shfl_sync(0xffffffffu, sc[ks][2], src0, 4);
            float v3 = __shfl_sync(0xffffffffu, sc[ks][3], src0, 4);
            float w0 = __shfl_sync(0xffffffffu, sc[ks][0], src1, 4);
            float w1 = __shfl_sync(0xffffffffu, sc[ks][1], src1, 4);
            float w2 = __shfl_sync(0xffffffffu, sc[ks][2], src1, 4);
            float w3 = __shfl_sync(0xffffffffu, sc[ks][3], src1, 4);
            bool odd = (t & 1);
            uint32_t pa0 = f2tf32(odd ? v1 : v0);
            uint32_t pa1 = f2tf32(odd ? v3 : v2);
            uint32_t pa2 = f2tf32(odd ? w1 : w0);
            uint32_t pa3 = f2tf32(odd ? w3 : w2);
            #pragma unroll
            for (int nd = 0; nd < 4; nd++) {
                uint32_t b0 = Vt[nd * 8 + g][ks * 8 + t];
                uint32_t b1 = Vt[nd * 8 + g][ks * 8 + t + 4];
                mma8(oacc[nd], pa0, pa1, pa2, pa3, b0, b1);
            }
        }
    }

    ol0 += __shfl_xor_sync(0xffffffffu, ol0, 1);
    ol0 += __shfl_xor_sync(0xffffffffu, ol0, 2);
    ol1 += __shfl_xor_sync(0xffffffffu, ol1, 1);
    ol1 += __shfl_xor_sync(0xffffffffu, ol1, 2);

    size_t pbase = ((size_t)((b * HH + h) * S + sp)) * QQ;
    if (qg < QQ) {
        if (t == 0) { pm[pbase + qg] = om0; pl[pbase + qg] = ol0; }
        float* ap = pacc + (pbase + qg) * HD;
        #pragma unroll
        for (int nd = 0; nd < 4; nd++)
            *reinterpret_cast<float2*>(ap + nd * 8 + 2 * t) =
                make_float2(oacc[nd][0], oacc[nd][1]);
    }
    if (qg8 < QQ) {
        if (t == 0) { pm[pbase + qg8] = om1; pl[pbase + qg8] = ol1; }
        float* ap = pacc + (pbase + qg8) * HD;
        #pragma unroll
        for (int nd = 0; nd < 4; nd++)
            *reinterpret_cast<float2*>(ap + nd * 8 + 2 * t) =
                make_float2(oacc[nd][2], oacc[nd][3]);
    }
}

// ---------------- split combine (parallel over d-pairs) ----------------
__global__ __launch_bounds__(256) void attn_combine_kernel(
    const float* __restrict__ pm, const float* __restrict__ pl,
    const float* __restrict__ pacc, int S, float* __restrict__ out)
{
    int tt = blockIdx.x * 256 + threadIdx.x;
    if (tt >= BB * HH * QQ * (HD / 2)) return;
    int dp = tt & (HD / 2 - 1);
    int idx = tt >> 4;
    int q = idx % QQ;
    int bh = idx / QQ;
    int b = bh / HH, h = bh % HH;

    float mg = -INFINITY;
    for (int s = 0; s < S; s++)
        mg = fmaxf(mg, pm[((size_t)bh * S + s) * QQ + q]);
    float Lsum = 0.f;
    float olo = 0.f, ohi = 0.f;
    for (int s = 0; s < S; s++) {
        size_t pidx = ((size_t)bh * S + s) * QQ + q;
        float w = __expf(pm[pidx] - mg);
        Lsum += pl[pidx] * w;
        float2 a = *reinterpret_cast<const float2*>(pacc + pidx * HD + 2 * dp);
        olo += w * a.x; ohi += w * a.y;
    }
    float inv = 1.f / Lsum;
    float2* op = reinterpret_cast<float2*>(
        out + ((size_t)(b * QQ + q)) * DD + h * HD + 2 * dp);
    *op = make_float2(olo * inv, ohi * inv);
}

// ---------------- host launcher ----------------
static inline int cdiv(int a, int b) { return (a + b - 1) / b; }

extern "C" void kernel_launch(void* const* d_in, const int* in_sizes, int n_in,
                              void* d_out, int out_size)
{
    const float* queries   = (const float*)d_in[0];
    const float* memory    = (const float*)d_in[1];
    const float* memory_pos= (const float*)d_in[2];
    const float* query_pos = (const float*)d_in[3];
    const float* sa_in_w   = (const float*)d_in[4];
    const float* sa_in_b   = (const float*)d_in[5];
    const float* sa_out_w  = (const float*)d_in[6];
    const float* sa_out_b  = (const float*)d_in[7];
    const float* norm1_g   = (const float*)d_in[8];
    const float* norm1_b   = (const float*)d_in[9];
    const float* q_w       = (const float*)d_in[10];
    const float* q_b       = (const float*)d_in[11];
    const float* k_w       = (const float*)d_in[12];
    const float* k_b       = (const float*)d_in[13];
    const float* v_w       = (const float*)d_in[14];
    const float* v_b       = (const float*)d_in[15];
    const float* o_w       = (const float*)d_in[16];
    const float* o_b       = (const float*)d_in[17];
    const float* norm2_g   = (const float*)d_in[18];
    const float* norm2_b   = (const float*)d_in[19];
    const float* beta      = (const float*)d_in[20];
    const float* dk_w1     = (const float*)d_in[21];
    const float* dk_b1     = (const float*)d_in[22];
    const float* dk_w2     = (const float*)d_in[23];
    const float* dk_b2     = (const float*)d_in[24];
    const float* ffn_w1    = (const float*)d_in[25];
    const float* ffn_b1    = (const float*)d_in[26];
    const float* ffn_w2    = (const float*)d_in[27];
    const float* ffn_b2    = (const float*)d_in[28];
    const float* norm3_g   = (const float*)d_in[29];
    const float* norm3_b   = (const float*)d_in[30];

    float *g_qkv, *g_sa, *g_tmp, *g_x1, *g_x2, *g_q, *g_k, *g_v, *g_bias,
          *g_ca, *g_ffn, *g_part, *g_pm, *g_pl, *g_pacc;
    cudaGetSymbolAddress((void**)&g_qkv,  s_qkv);
    cudaGetSymbolAddress((void**)&g_sa,   s_sa);
    cudaGetSymbolAddress((void**)&g_tmp,  s_tmp);
    cudaGetSymbolAddress((void**)&g_x1,   s_x1);
    cudaGetSymbolAddress((void**)&g_x2,   s_x2);
    cudaGetSymbolAddress((void**)&g_q,    s_q);
    cudaGetSymbolAddress((void**)&g_k,    s_k);
    cudaGetSymbolAddress((void**)&g_v,    s_v);
    cudaGetSymbolAddress((void**)&g_bias, s_bias);
    cudaGetSymbolAddress((void**)&g_ca,   s_ca);
    cudaGetSymbolAddress((void**)&g_ffn,  s_ffn);
    cudaGetSymbolAddress((void**)&g_part, s_part);
    cudaGetSymbolAddress((void**)&g_pm,   s_pm);
    cudaGetSymbolAddress((void**)&g_pl,   s_pl);
    cudaGetSymbolAddress((void**)&g_pacc, s_pacc);

    // side streams + events (created once, outside capture on first call)
    static cudaStream_t st2 = nullptr, st3 = nullptr;
    static cudaEvent_t ev0 = nullptr, ev2 = nullptr, ev3 = nullptr;
    if (st2 == nullptr) {
        cudaStreamCreateWithFlags(&st2, cudaStreamNonBlocking);
        cudaStreamCreateWithFlags(&st3, cudaStreamNonBlocking);
        cudaEventCreateWithFlags(&ev0, cudaEventDisableTiming);
        cudaEventCreateWithFlags(&ev2, cudaEventDisableTiming);
        cudaEventCreateWithFlags(&ev3, cudaEventDisableTiming);
    }

    const int Mq = BB * QQ;   // 2400
    const int Mm = BB * LL;   // 8192
    const int NCOMB = BB * HH * QQ * (HD / 2);

    // ---- fork: KV-proj and GASA bias depend only on inputs ----
    cudaEventRecord(ev0, 0);
    cudaStreamWaitEvent(st2, ev0, 0);
    cudaStreamWaitEvent(st3, ev0, 0);

    gemm_tf32_kernel<2><<<dim3(2 * DD / 64, cdiv(Mm, 128), 1), 256, 0, st2>>>(
        memory, k_w, k_b, g_k, Mm, DD, DD, 0, v_w, v_b, g_v);
    cudaEventRecord(ev2, st2);

    gasa_bias_kernel<<<dim3(LL, BB), 128, 0, st3>>>(
        query_pos, memory_pos, dk_w1, dk_b1, dk_w2, dk_b2, beta, g_bias);
    cudaEventRecord(ev3, st3);

    // ---- main chain (default stream) ----
    // 1) self-attn packed in-proj
    gemm_tf32_kernel<2><<<dim3(3 * DD / 64, cdiv(Mq, 128), 1), 256>>>(
        queries, sa_in_w, sa_in_b, g_qkv, Mq, 3 * DD, DD, 0);

    // 2) self-attention (no bias), split S=2
    {
        int S = 2, step = cdiv(QQ, S * 16) * 16;   // 304
        attn_mma_kernel<<<dim3(NQT * S, HH, BB), 128>>>(
            g_qkv, 3 * DD, g_qkv + DD, g_qkv + 2 * DD, 3 * DD,
            nullptr, QQ, S, step, g_pm, g_pl, g_pacc, 0);
        attn_combine_kernel<<<cdiv(NCOMB, 256), 256>>>(g_pm, g_pl, g_pacc, S, g_sa);
    }

    // 3) SA out-proj + LN1
    gemm_tf32_kernel<1><<<dim3(DD / 64, cdiv(Mq, 64), 1), 256>>>(
        g_sa, sa_out_w, sa_out_b, g_tmp, Mq, DD, DD, 0);
    ln_kernel<<<Mq, 256>>>(queries, g_tmp, norm1_g, norm1_b, g_x1);

    // 4) Q projection
    gemm_tf32_kernel<1><<<dim3(DD / 64, cdiv(Mq, 64), 1), 256>>>(
        g_x1, q_w, q_b, g_q, Mq, DD, DD, 0);

    // ---- join ----
    cudaStreamWaitEvent(0, ev2, 0);
    cudaStreamWaitEvent(0, ev3, 0);

    // 5) cross-attention with bias, split S=4 (step 512)
    {
        int S = 4, step = cdiv(LL, S * 16) * 16;
        attn_mma_kernel<<<dim3(NQT * S, HH, BB), 128>>>(
            g_q, DD, g_k, g_v, DD, g_bias, LL, S, step, g_pm, g_pl, g_pacc, 1);
        attn_combine_kernel<<<cdiv(NCOMB, 256), 256>>>(g_pm, g_pl, g_pacc, S, g_ca);
    }

    // 6) O proj + LN2
    gemm_tf32_kernel<1><<<dim3(DD / 64, cdiv(Mq, 64), 1), 256>>>(
        g_ca, o_w, o_b, g_tmp, Mq, DD, DD, 0);
    ln_kernel<<<Mq, 256>>>(g_x1, g_tmp, norm2_g, norm2_b, g_x2);

    // 7) FFN1 (relu)
    gemm_tf32_kernel<2><<<dim3(DFF / 64, cdiv(Mq, 128), 1), 256>>>(
        g_x2, ffn_w1, ffn_b1, g_ffn, Mq, DFF, DD, 1);

    // 8) FFN2 split-K=4 partials + fused combine in LN3 -> output
    gemm_tf32_kernel<1><<<dim3(DD / 64, cdiv(Mq, 64), 4), 256>>>(
        g_ffn, ffn_w2, ffn_b2, g_part, Mq, DD, DFF, 0);
    ln_split_kernel<<<Mq, 256>>>(g_x2, g_part, ffn_b2, norm3_g, norm3_b,
                                 (float*)d_out, 4);
}

// round 8
// speedup vs baseline: 1.2230x; 1.0492x over previous
#include <cuda_runtime.h>
#include <cuda_fp16.h>
#include <math.h>
#include <stdint.h>

// ---------------- problem constants ----------------
#define BB 4
#define QQ 600
#define LL 2048
#define DD 256
#define HH 8
#define HD 32
#define DFF 2048
#define KD 32
#define SCALE 0.17677669529663687f   // 32^-0.5
#define NQT 10                       // ceil(600/64) 64-query tiles

typedef unsigned long long u64;

// ---------------- helpers ----------------
__device__ __forceinline__ uint32_t f2tf32(float x) {
    uint32_t u; asm("cvt.rna.tf32.f32 %0, %1;" : "=r"(u) : "f"(x)); return u;
}
__device__ __forceinline__ void mma8(float c[4], uint32_t a0, uint32_t a1,
                                     uint32_t a2, uint32_t a3,
                                     uint32_t b0, uint32_t b1) {
    asm("mma.sync.aligned.m16n8k8.row.col.f32.tf32.tf32.f32 "
        "{%0,%1,%2,%3},{%4,%5,%6,%7},{%8,%9},{%0,%1,%2,%3};"
        : "+f"(c[0]), "+f"(c[1]), "+f"(c[2]), "+f"(c[3])
        : "r"(a0), "r"(a1), "r"(a2), "r"(a3), "r"(b0), "r"(b1));
}
__device__ __forceinline__ void mma16h(float c[4], uint32_t a0, uint32_t a1,
                                       uint32_t a2, uint32_t a3,
                                       uint32_t b0, uint32_t b1) {
    asm("mma.sync.aligned.m16n8k16.row.col.f32.f16.f16.f32 "
        "{%0,%1,%2,%3},{%4,%5,%6,%7},{%8,%9},{%0,%1,%2,%3};"
        : "+f"(c[0]), "+f"(c[1]), "+f"(c[2]), "+f"(c[3])
        : "r"(a0), "r"(a1), "r"(a2), "r"(a3), "r"(b0), "r"(b1));
}
__device__ __forceinline__ void cp16(uint32_t dst, const void* src, int srcsize) {
    asm volatile("cp.async.ca.shared.global [%0], [%1], 16, %2;"
                 :: "r"(dst), "l"(src), "r"(srcsize));
}
__device__ __forceinline__ void cp_commit() {
    asm volatile("cp.async.commit_group;");
}
template<int N>
__device__ __forceinline__ void cp_wait() {
    asm volatile("cp.async.wait_group %0;" :: "n"(N));
}

// ---------------- scratch (device globals) ----------------
__device__ float s_qkv [BB*QQ*3*DD];
__device__ float s_tmp [BB*QQ*DD];
__device__ float s_x1  [BB*QQ*DD];
__device__ float s_x2  [BB*QQ*DD];
__device__ float s_q   [BB*QQ*DD];
__device__ float s_k   [BB*LL*DD];
__device__ float s_v   [BB*LL*DD];
__device__ float s_bias[BB*LL*QQ];
__device__ float s_part[4*BB*QQ*DD];
__device__ float s_pm  [BB*HH*8*QQ];
__device__ float s_pl  [BB*HH*8*QQ];
__device__ float s_pacc[BB*HH*8*QQ*HD];
// fp16 copies
__device__ __half h_queries[BB*QQ*DD];
__device__ __half h_memory [BB*LL*DD];
__device__ __half h_sa_in_w[3*DD*DD];
__device__ __half h_sa_out_w[DD*DD];
__device__ __half h_q_w[DD*DD];
__device__ __half h_k_w[DD*DD];
__device__ __half h_v_w[DD*DD];
__device__ __half h_o_w[DD*DD];
__device__ __half h_ffn_w1[DFF*DD];
__device__ __half h_ffn_w2[DD*DFF];
__device__ __half h_sa [BB*QQ*DD];
__device__ __half h_ca [BB*QQ*DD];
__device__ __half h_x1 [BB*QQ*DD];
__device__ __half h_x2 [BB*QQ*DD];
__device__ __half h_ffn[BB*QQ*DFF];

// ---------------- fp32 -> fp16 convert (8 elts/thread) ----------------
__global__ __launch_bounds__(256) void f2h_kernel(
    const float* __restrict__ src, __half* __restrict__ dst, int n)
{
    int i = (blockIdx.x * 256 + threadIdx.x) * 8;
    if (i >= n) return;
    float4 x0 = *reinterpret_cast<const float4*>(src + i);
    float4 x1 = *reinterpret_cast<const float4*>(src + i + 4);
    __half2 h0 = __floats2half2_rn(x0.x, x0.y);
    __half2 h1 = __floats2half2_rn(x0.z, x0.w);
    __half2 h2 = __floats2half2_rn(x1.x, x1.y);
    __half2 h3 = __floats2half2_rn(x1.z, x1.w);
    uint4 u;
    u.x = *reinterpret_cast<uint32_t*>(&h0);
    u.y = *reinterpret_cast<uint32_t*>(&h1);
    u.z = *reinterpret_cast<uint32_t*>(&h2);
    u.w = *reinterpret_cast<uint32_t*>(&h3);
    *reinterpret_cast<uint4*>(dst + i) = u;
}

// ---------------- FP16 tensor-core GEMM (3-stage cp.async pipeline) -------
// C[M,N] = A[M,K] @ W[N,K]^T (+bias, opt relu). A/W fp16, accum fp32.
// Outputs: C (fp32, optional) and/or Ch (fp16, optional).
// MF = m-frags per warp (1 -> BM=64, 2 -> BM=128). grid.z = split-K count.
// DUAL: if W2 != nullptr, blockIdx.x >= N/64 uses W2/bias2/C2/C2h.
#define KP 24      // halves per smem row (48B: 16B-aligned, conflict-free)
#define NST 3

template<int MF>
__global__ __launch_bounds__(256) void gemm_f16_kernel(
    const __half* __restrict__ A, const __half* __restrict__ W,
    const float* __restrict__ bias, float* C, __half* Ch,
    int M, int N, int K, int relu,
    const __half* __restrict__ W2 = nullptr,
    const float* __restrict__ bias2 = nullptr,
    float* C2 = nullptr, __half* C2h = nullptr)
{
    __shared__ __align__(16) __half As[NST][64 * MF][KP];
    __shared__ __align__(16) __half Ws[NST][64][KP];

    const int tid = threadIdx.x;
    const int lane = tid & 31;
    const int w = tid >> 5;
    const int wm = w & 3;
    const int wn = w >> 2;
    const int g = lane >> 2;
    const int t = lane & 3;

    int bx = blockIdx.x;
    const int nblk = N / 64;
    if (W2 != nullptr && bx >= nblk) {
        bx -= nblk;
        W = W2; bias = bias2; C = C2; Ch = C2h;
    }

    const int m0 = blockIdx.y * (64 * MF);
    const int n0 = bx * 64;

    const int nsplit = gridDim.z;
    const int Klen = K / nsplit;
    const int kstart = blockIdx.z * Klen;
    float* Cout = (C && nsplit > 1) ? (C + (size_t)blockIdx.z * M * N) : C;

    const uint32_t as_base = (uint32_t)__cvta_generic_to_shared(&As[0][0][0]);
    const uint32_t ws_base = (uint32_t)__cvta_generic_to_shared(&Ws[0][0][0]);

    float acc[MF][4][4];
    #pragma unroll
    for (int i = 0; i < MF; i++)
        #pragma unroll
        for (int j = 0; j < 4; j++)
            #pragma unroll
            for (int e = 0; e < 4; e++) acc[i][j][e] = 0.f;

    const int m_warp = wm * (16 * MF);
    const int n_warp = wn * 32;
    const int nIter = Klen / 16;

    // stage loader: 16 k-halves per row = 32B = 2 cp16 per row
    auto load_stage = [&](int st, int it) {
        const int kg = kstart + it * 16;
        if (MF == 2) {
            // A: 128 rows, 256 cp16 -> all threads
            int r = tid >> 1, kc = (tid & 1) * 8;
            int arow = m0 + r;
            uint32_t dst = as_base + ((st * 128 + r) * KP + kc) * 2;
            cp16(dst, A + (size_t)arow * K + kg + kc, (arow < M) ? 16 : 0);
            // W: 64 rows, 128 cp16 -> threads 0..127
            if (tid < 128) {
                int wr = tid >> 1, wkc = (tid & 1) * 8;
                uint32_t d2 = ws_base + ((st * 64 + wr) * KP + wkc) * 2;
                cp16(d2, W + (size_t)(n0 + wr) * K + kg + wkc, 16);
            }
        } else {
            if (tid < 128) {
                int r = tid >> 1, kc = (tid & 1) * 8;
                int arow = m0 + r;
                uint32_t dst = as_base + ((st * 64 + r) * KP + kc) * 2;
                cp16(dst, A + (size_t)arow * K + kg + kc, (arow < M) ? 16 : 0);
            } else {
                int r = (tid - 128) >> 1, kc = (tid & 1) * 8;
                uint32_t dst = ws_base + ((st * 64 + r) * KP + kc) * 2;
                cp16(dst, W + (size_t)(n0 + r) * K + kg + kc, 16);
            }
        }
        cp_commit();
    };

    load_stage(0, 0);
    load_stage(1, 1);

    for (int it = 0; it < nIter; it++) {
        cp_wait<NST - 2>();
        __syncthreads();
        if (it + NST - 1 < nIter) load_stage((it + NST - 1) % NST, it + NST - 1);
        else cp_commit();

        const int st = it % NST;
        uint32_t b0[4], b1[4];
        #pragma unroll
        for (int ni = 0; ni < 4; ni++) {
            b0[ni] = *reinterpret_cast<const uint32_t*>(&Ws[st][n_warp + ni * 8 + g][2 * t]);
            b1[ni] = *reinterpret_cast<const uint32_t*>(&Ws[st][n_warp + ni * 8 + g][8 + 2 * t]);
        }
        #pragma unroll
        for (int mi = 0; mi < MF; mi++) {
            int mb = m_warp + mi * 16;
            uint32_t a0 = *reinterpret_cast<const uint32_t*>(&As[st][mb + g][2 * t]);
            uint32_t a1 = *reinterpret_cast<const uint32_t*>(&As[st][mb + g + 8][2 * t]);
            uint32_t a2 = *reinterpret_cast<const uint32_t*>(&As[st][mb + g][8 + 2 * t]);
            uint32_t a3 = *reinterpret_cast<const uint32_t*>(&As[st][mb + g + 8][8 + 2 * t]);
            #pragma unroll
            for (int ni = 0; ni < 4; ni++)
                mma16h(acc[mi][ni], a0, a1, a2, a3, b0[ni], b1[ni]);
        }
    }

    #pragma unroll
    for (int mi = 0; mi < MF; mi++) {
        #pragma unroll
        for (int ni = 0; ni < 4; ni++) {
            int col = n0 + n_warp + ni * 8 + 2 * t;
            float bz0 = 0.f, bz1 = 0.f;
            if (nsplit == 1) { bz0 = bias[col]; bz1 = bias[col + 1]; }
            int r0 = m0 + m_warp + mi * 16 + g;
            int r1 = r0 + 8;
            float v0 = acc[mi][ni][0] + bz0, v1 = acc[mi][ni][1] + bz1;
            float v2 = acc[mi][ni][2] + bz0, v3 = acc[mi][ni][3] + bz1;
            if (relu) {
                v0 = fmaxf(v0, 0.f); v1 = fmaxf(v1, 0.f);
                v2 = fmaxf(v2, 0.f); v3 = fmaxf(v3, 0.f);
            }
            if (Cout) {
                if (r0 < M) *reinterpret_cast<float2*>(Cout + (size_t)r0 * N + col) = make_float2(v0, v1);
                if (r1 < M) *reinterpret_cast<float2*>(Cout + (size_t)r1 * N + col) = make_float2(v2, v3);
            }
            if (Ch) {
                if (r0 < M) {
                    __half2 hv = __floats2half2_rn(v0, v1);
                    *reinterpret_cast<uint32_t*>(Ch + (size_t)r0 * N + col) =
                        *reinterpret_cast<uint32_t*>(&hv);
                }
                if (r1 < M) {
                    __half2 hv = __floats2half2_rn(v2, v3);
                    *reinterpret_cast<uint32_t*>(Ch + (size_t)r1 * N + col) =
                        *reinterpret_cast<uint32_t*>(&hv);
                }
            }
        }
    }
}

// ---------------- warp-per-row LayerNorm (8 rows / 256-thread block) ------
__device__ __forceinline__ void lnw_finish(
    float v[8], int lane, const float* g, const float* bt,
    float* out, __half* outh, size_t row)
{
    float s1 = 0.f, s2 = 0.f;
    #pragma unroll
    for (int i = 0; i < 8; i++) { s1 += v[i]; s2 += v[i] * v[i]; }
    #pragma unroll
    for (int o = 16; o > 0; o >>= 1) {
        s1 += __shfl_xor_sync(0xffffffffu, s1, o);
        s2 += __shfl_xor_sync(0xffffffffu, s2, o);
    }
    float mean = s1 * (1.f / DD);
    float var = s2 * (1.f / DD) - mean * mean;
    float rstd = rsqrtf(var + 1e-5f);
    int c0 = lane * 8;
    float r[8];
    #pragma unroll
    for (int i = 0; i < 8; i++)
        r[i] = (v[i] - mean) * rstd * g[c0 + i] + bt[c0 + i];
    if (out) {
        *reinterpret_cast<float4*>(out + row * DD + c0) = make_float4(r[0], r[1], r[2], r[3]);
        *reinterpret_cast<float4*>(out + row * DD + c0 + 4) = make_float4(r[4], r[5], r[6], r[7]);
    }
    if (outh) {
        __half2 h0 = __floats2half2_rn(r[0], r[1]);
        __half2 h1 = __floats2half2_rn(r[2], r[3]);
        __half2 h2 = __floats2half2_rn(r[4], r[5]);
        __half2 h3 = __floats2half2_rn(r[6], r[7]);
        uint4 u;
        u.x = *reinterpret_cast<uint32_t*>(&h0);
        u.y = *reinterpret_cast<uint32_t*>(&h1);
        u.z = *reinterpret_cast<uint32_t*>(&h2);
        u.w = *reinterpret_cast<uint32_t*>(&h3);
        *reinterpret_cast<uint4*>(outh + row * DD + c0) = u;
    }
}

__global__ __launch_bounds__(256) void ln_kernel(
    const float* __restrict__ A, const float* __restrict__ R,
    const float* __restrict__ g, const float* __restrict__ bt,
    float* out, __half* outh)
{
    const int lane = threadIdx.x & 31;
    const size_t row = blockIdx.x * 8 + (threadIdx.x >> 5);
    int c0 = lane * 8;
    float4 a0 = *reinterpret_cast<const float4*>(A + row * DD + c0);
    float4 a1 = *reinterpret_cast<const float4*>(A + row * DD + c0 + 4);
    float4 r0 = *reinterpret_cast<const float4*>(R + row * DD + c0);
    float4 r1 = *reinterpret_cast<const float4*>(R + row * DD + c0 + 4);
    float v[8] = { a0.x + r0.x, a0.y + r0.y, a0.z + r0.z, a0.w + r0.w,
                   a1.x + r1.x, a1.y + r1.y, a1.z + r1.z, a1.w + r1.w };
    lnw_finish(v, lane, g, bt, out, outh, row);
}

__global__ __launch_bounds__(256) void ln_split_kernel(
    const float* __restrict__ X, const float* __restrict__ parts,
    const float* __restrict__ fbias,
    const float* __restrict__ g, const float* __restrict__ bt,
    float* out, int nsplit)
{
    const int lane = threadIdx.x & 31;
    const size_t row = blockIdx.x * 8 + (threadIdx.x >> 5);
    const size_t stride = (size_t)BB * QQ * DD;
    int c0 = lane * 8;
    float v[8];
    float4 x0 = *reinterpret_cast<const float4*>(X + row * DD + c0);
    float4 x1 = *reinterpret_cast<const float4*>(X + row * DD + c0 + 4);
    float4 f0 = *reinterpret_cast<const float4*>(fbias + c0);
    float4 f1 = *reinterpret_cast<const float4*>(fbias + c0 + 4);
    v[0] = x0.x + f0.x; v[1] = x0.y + f0.y; v[2] = x0.z + f0.z; v[3] = x0.w + f0.w;
    v[4] = x1.x + f1.x; v[5] = x1.y + f1.y; v[6] = x1.z + f1.z; v[7] = x1.w + f1.w;
    for (int s = 0; s < nsplit; s++) {
        float4 p0 = *reinterpret_cast<const float4*>(parts + s * stride + row * DD + c0);
        float4 p1 = *reinterpret_cast<const float4*>(parts + s * stride + row * DD + c0 + 4);
        v[0] += p0.x; v[1] += p0.y; v[2] += p0.z; v[3] += p0.w;
        v[4] += p1.x; v[5] += p1.y; v[6] += p1.z; v[7] += p1.w;
    }
    lnw_finish(v, lane, g, bt, out, nullptr, row);
}

// ---------------- GASA geometric bias: block per (b,l) ----------------
__global__ __launch_bounds__(128) void gasa_bias_kernel(
    const float* __restrict__ qpos, const float* __restrict__ mpos,
    const float* __restrict__ w1, const float* __restrict__ b1,
    const float* __restrict__ w2, const float* __restrict__ b2,
    const float* __restrict__ betap, float* __restrict__ biasT)
{
    const int l = blockIdx.x;
    const int b = blockIdx.y;
    const int tid = threadIdx.x;

    __shared__ float sw1[KD], sb1[KD], sw2[KD], smp[3], sb2, sbeta;
    if (tid < KD) {
        sw1[tid] = w1[tid];
        sb1[tid] = b1[tid];
        sw2[tid] = w2[tid];
    }
    if (tid < 3) smp[tid] = mpos[((size_t)b * LL + l) * 3 + tid];
    if (tid == 3) sb2 = b2[0];
    if (tid == 4) sbeta = betap[0];
    __syncthreads();

    const float mx = smp[0], my = smp[1], mz = smp[2];
    const float bb2 = sb2, bet = sbeta;
    float* orow = biasT + ((size_t)b * LL + l) * QQ;

    for (int q = tid; q < QQ; q += 128) {
        const float* qp = qpos + ((size_t)b * QQ + q) * 3;
        float dx = qp[0] - mx, dy = qp[1] - my, dz = qp[2] - mz;
        float dist = sqrtf(fmaxf(dx * dx + dy * dy + dz * dz, 0.f));
        float s = 0.f;
        #pragma unroll
        for (int k = 0; k < KD; k++) {
            float h = fmaxf(dist * sw1[k] + sb1[k], 0.f);
            s += h * sw2[k];
        }
        s += bb2;
        s = fminf(fmaxf(s, -10.f), 0.f);
        orow[q] = s * bet;
    }
}

// ---------------- tensor-core flash attention partials ----------------
__global__ __launch_bounds__(128) void attn_mma_kernel(
    const float* __restrict__ Qp, int qstride,
    const float* __restrict__ Kp, const float* __restrict__ Vp, int kvstride,
    const float* __restrict__ biasT, int Lk, int S, int step,
    float* __restrict__ pm, float* __restrict__ pl, float* __restrict__ pacc,
    int useBias)
{
    const int b = blockIdx.z, h = blockIdx.y;
    const int sp = blockIdx.x / NQT;
    const int qt = blockIdx.x % NQT;
    const int tid = threadIdx.x;
    const int lane = tid & 31;
    const int warp = tid >> 5;
    const int g = lane >> 2;
    const int t = lane & 3;

    const int q0 = qt * 64 + warp * 16;
    const int qg  = q0 + g;
    const int qg8 = q0 + g + 8;
    const int qgc  = min(qg, QQ - 1);
    const int qg8c = min(qg8, QQ - 1);

    const int ls = sp * step;
    const int le = min(ls + step, Lk);

    uint32_t qa[4][4];
    {
        const float* q0p = Qp + ((size_t)(b * QQ + qgc)) * qstride + h * HD;
        const float* q1p = Qp + ((size_t)(b * QQ + qg8c)) * qstride + h * HD;
        #pragma unroll
        for (int ks = 0; ks < 4; ks++) {
            qa[ks][0] = f2tf32(q0p[ks * 8 + t] * SCALE);
            qa[ks][1] = f2tf32(q1p[ks * 8 + t] * SCALE);
            qa[ks][2] = f2tf32(q0p[ks * 8 + t + 4] * SCALE);
            qa[ks][3] = f2tf32(q1p[ks * 8 + t + 4] * SCALE);
        }
    }

    __shared__ uint32_t Ks[16][36];
    __shared__ uint32_t Vt[HD][17];
    __shared__ float    Bsm[16][68];

    float oacc[4][4];
    #pragma unroll
    for (int i = 0; i < 4; i++)
        #pragma unroll
        for (int j = 0; j < 4; j++) oacc[i][j] = 0.f;
    float om0 = -INFINITY, om1 = -INFINITY;
    float ol0 = 0.f, ol1 = 0.f;

    const int key_l = tid >> 3;
    const int d0 = (tid & 7) * 4;
    const int bq0 = (tid & 7) * 8;
    const bool qtail = (qt == NQT - 1);

    float4 kreg, vreg, breg0, breg1;

    auto prefetch = [&](int l0) {
        int grow = b * Lk + min(l0 + key_l, Lk - 1);
        kreg = *reinterpret_cast<const float4*>(
            Kp + (size_t)grow * kvstride + h * HD + d0);
        vreg = *reinterpret_cast<const float4*>(
            Vp + (size_t)grow * kvstride + h * HD + d0);
        if (useBias) {
            const float* brow = biasT + ((size_t)(b * Lk + l0 + key_l)) * QQ
                                + qt * 64 + bq0;
            if (!qtail) {
                breg0 = *reinterpret_cast<const float4*>(brow);
                breg1 = *reinterpret_cast<const float4*>(brow + 4);
            } else {
                int qb = qt * 64 + bq0;
                float e[8];
                #pragma unroll
                for (int i = 0; i < 8; i++)
                    e[i] = (qb + i < QQ) ? brow[i] : 0.f;
                breg0 = make_float4(e[0], e[1], e[2], e[3]);
                breg1 = make_float4(e[4], e[5], e[6], e[7]);
            }
        }
    };

    prefetch(ls);

    for (int l0 = ls; l0 < le; l0 += 16) {
        __syncthreads();
        {
            uint4 ku = make_uint4(f2tf32(kreg.x), f2tf32(kreg.y),
                                  f2tf32(kreg.z), f2tf32(kreg.w));
            *reinterpret_cast<uint4*>(&Ks[key_l][d0]) = ku;
            Vt[d0 + 0][key_l] = f2tf32(vreg.x);
            Vt[d0 + 1][key_l] = f2tf32(vreg.y);
            Vt[d0 + 2][key_l] = f2tf32(vreg.z);
            Vt[d0 + 3][key_l] = f2tf32(vreg.w);
            if (useBias) {
                *reinterpret_cast<float4*>(&Bsm[key_l][bq0]) = breg0;
                *reinterpret_cast<float4*>(&Bsm[key_l][bq0 + 4]) = breg1;
            }
        }
        if (l0 + 16 < le) prefetch(l0 + 16);
        __syncthreads();

        float sc[2][4];
        #pragma unroll
        for (int nf = 0; nf < 2; nf++) {
            sc[nf][0] = sc[nf][1] = sc[nf][2] = sc[nf][3] = 0.f;
            #pragma unroll
            for (int ks = 0; ks < 4; ks++) {
                uint32_t b0 = Ks[nf * 8 + g][ks * 8 + t];
                uint32_t b1 = Ks[nf * 8 + g][ks * 8 + t + 4];
                mma8(sc[nf], qa[ks][0], qa[ks][1], qa[ks][2], qa[ks][3], b0, b1);
            }
        }

        #pragma unroll
        for (int nf = 0; nf < 2; nf++) {
            if (useBias) {
                int brow = nf * 8 + 2 * t;
                int c0 = warp * 16 + g;
                sc[nf][0] += Bsm[brow][c0];
                sc[nf][1] += Bsm[brow + 1][c0];
                sc[nf][2] += Bsm[brow][c0 + 8];
                sc[nf][3] += Bsm[brow + 1][c0 + 8];
            }
            int kc = l0 + nf * 8 + 2 * t;
            if (kc >= le)     { sc[nf][0] = -1e30f; sc[nf][2] = -1e30f; }
            if (kc + 1 >= le) { sc[nf][1] = -1e30f; sc[nf][3] = -1e30f; }
        }

        float mx0 = fmaxf(fmaxf(sc[0][0], sc[0][1]), fmaxf(sc[1][0], sc[1][1]));
        float mx1 = fmaxf(fmaxf(sc[0][2], sc[0][3]), fmaxf(sc[1][2], sc[1][3]));
        mx0 = fmaxf(mx0, __shfl_xor_sync(0xffffffffu, mx0, 1));
        mx0 = fmaxf(mx0, __shfl_xor_sync(0xffffffffu, mx0, 2));
        mx1 = fmaxf(mx1, __shfl_xor_sync(0xffffffffu, mx1, 1));
        mx1 = fmaxf(mx1, __shfl_xor_sync(0xffffffffu, mx1, 2));

        float nm0 = fmaxf(om0, mx0), nm1 = fmaxf(om1, mx1);
        float cr0 = __expf(om0 - nm0), cr1 = __expf(om1 - nm1);
        om0 = nm0; om1 = nm1;
        ol0 *= cr0; ol1 *= cr1;
        #pragma unroll
        for (int nd = 0; nd < 4; nd++) {
            oacc[nd][0] *= cr0; oacc[nd][1] *= cr0;
            oacc[nd][2] *= cr1; oacc[nd][3] *= cr1;
        }

        #pragma unroll
        for (int nf = 0; nf < 2; nf++) {
            sc[nf][0] = __expf(sc[nf][0] - nm0);
            sc[nf][1] = __expf(sc[nf][1] - nm0);
            sc[nf][2] = __expf(sc[nf][2] - nm1);
            sc[nf][3] = __expf(sc[nf][3] - nm1);
            ol0 += sc[nf][0] + sc[nf][1];
            ol1 += sc[nf][2] + sc[nf][3];
        }

        #pragma unroll
        for (int ks = 0; ks < 2; ks++) {
            int src0 = t >> 1, src1 = (t >> 1) + 2;
            float v0 = __shfl_sync(0xffffffffu, sc[ks][0], src0, 4);
            float v1 = __shfl_sync(0xffffffffu, sc[ks][1], src0, 4);
            float v2 = __shfl_sync(0xffffffffu, sc[ks][2], src0, 4);
            float v3 = __shfl_sync(0xffffffffu, sc[ks][3], src0, 4);
            float w0 = __shfl_sync(0xffffffffu, sc[ks][0], src1, 4);
            float w1 = __shfl_sync(0xffffffffu, sc[ks][1], src1, 4);
            float w2 = __shfl_sync(0xffffffffu, sc[ks][2], src1, 4);
            float w3 = __shfl_sync(0xffffffffu, sc[ks][3], src1, 4);
            bool odd = (t & 1);
            uint32_t pa0 = f2tf32(odd ? v1 : v0);
            uint32_t pa1 = f2tf32(odd ? v3 : v2);
            uint32_t pa2 = f2tf32(odd ? w1 : w0);
            uint32_t pa3 = f2tf32(odd ? w3 : w2);
            #pragma unroll
            for (int nd = 0; nd < 4; nd++) {
                uint32_t b0 = Vt[nd * 8 + g][ks * 8 + t];
                uint32_t b1 = Vt[nd * 8 + g][ks * 8 + t + 4];
                mma8(oacc[nd], pa0, pa1, pa2, pa3, b0, b1);
            }
        }
    }

    ol0 += __shfl_xor_sync(0xffffffffu, ol0, 1);
    ol0 += __shfl_xor_sync(0xffffffffu, ol0, 2);
    ol1 += __shfl_xor_sync(0xffffffffu, ol1, 1);
    ol1 += __shfl_xor_sync(0xffffffffu, ol1, 2);

    size_t pbase = ((size_t)((b * HH + h) * S + sp)) * QQ;
    if (qg < QQ) {
        if (t == 0) { pm[pbase + qg] = om0; pl[pbase + qg] = ol0; }
        float* ap = pacc + (pbase + qg) * HD;
        #pragma unroll
        for (int nd = 0; nd < 4; nd++)
            *reinterpret_cast<float2*>(ap + nd * 8 + 2 * t) =
                make_float2(oacc[nd][0], oacc[nd][1]);
    }
    if (qg8 < QQ) {
        if (t == 0) { pm[pbase + qg8] = om1; pl[pbase + qg8] = ol1; }
        float* ap = pacc + (pbase + qg8) * HD;
        #pragma unroll
        for (int nd = 0; nd < 4; nd++)
            *reinterpret_cast<float2*>(ap + nd * 8 + 2 * t) =
                make_float2(oacc[nd][2], oacc[nd][3]);
    }
}

// ---------------- split combine (writes fp16 for GEMM consumption) --------
__global__ __launch_bounds__(256) void attn_combine_kernel(
    const float* __restrict__ pm, const float* __restrict__ pl,
    const float* __restrict__ pacc, int S, __half* __restrict__ out)
{
    int tt = blockIdx.x * 256 + threadIdx.x;
    if (tt >= BB * HH * QQ * (HD / 2)) return;
    int dp = tt & (HD / 2 - 1);
    int idx = tt >> 4;
    int q = idx % QQ;
    int bh = idx / QQ;
    int b = bh / HH, h = bh % HH;

    float mg = -INFINITY;
    for (int s = 0; s < S; s++)
        mg = fmaxf(mg, pm[((size_t)bh * S + s) * QQ + q]);
    float Lsum = 0.f;
    float olo = 0.f, ohi = 0.f;
    for (int s = 0; s < S; s++) {
        size_t pidx = ((size_t)bh * S + s) * QQ + q;
        float w = __expf(pm[pidx] - mg);
        Lsum += pl[pidx] * w;
        float2 a = *reinterpret_cast<const float2*>(pacc + pidx * HD + 2 * dp);
        olo += w * a.x; ohi += w * a.y;
    }
    float inv = 1.f / Lsum;
    __half2 hv = __floats2half2_rn(olo * inv, ohi * inv);
    *reinterpret_cast<uint32_t*>(
        out + ((size_t)(b * QQ + q)) * DD + h * HD + 2 * dp) =
        *reinterpret_cast<uint32_t*>(&hv);
}

// ---------------- host launcher ----------------
static inline int cdiv(int a, int b) { return (a + b - 1) / b; }

extern "C" void kernel_launch(void* const* d_in, const int* in_sizes, int n_in,
                              void* d_out, int out_size)
{
    const float* queries   = (const float*)d_in[0];
    const float* memory    = (const float*)d_in[1];
    const float* memory_pos= (const float*)d_in[2];
    const float* query_pos = (const float*)d_in[3];
    const float* sa_in_w   = (const float*)d_in[4];
    const float* sa_in_b   = (const float*)d_in[5];
    const float* sa_out_w  = (const float*)d_in[6];
    const float* sa_out_b  = (const float*)d_in[7];
    const float* norm1_g   = (const float*)d_in[8];
    const float* norm1_b   = (const float*)d_in[9];
    const float* q_w       = (const float*)d_in[10];
    const float* q_b       = (const float*)d_in[11];
    const float* k_w       = (const float*)d_in[12];
    const float* k_b       = (const float*)d_in[13];
    const float* v_w       = (const float*)d_in[14];
    const float* v_b       = (const float*)d_in[15];
    const float* o_w       = (const float*)d_in[16];
    const float* o_b       = (const float*)d_in[17];
    const float* norm2_g   = (const float*)d_in[18];
    const float* norm2_b   = (const float*)d_in[19];
    const float* beta      = (const float*)d_in[20];
    const float* dk_w1     = (const float*)d_in[21];
    const float* dk_b1     = (const float*)d_in[22];
    const float* dk_w2     = (const float*)d_in[23];
    const float* dk_b2     = (const float*)d_in[24];
    const float* ffn_w1    = (const float*)d_in[25];
    const float* ffn_b1    = (const float*)d_in[26];
    const float* ffn_w2    = (const float*)d_in[27];
    const float* ffn_b2    = (const float*)d_in[28];
    const float* norm3_g   = (const float*)d_in[29];
    const float* norm3_b   = (const float*)d_in[30];

    float *g_qkv, *g_tmp, *g_x1, *g_x2, *g_q, *g_k, *g_v, *g_bias,
          *g_part, *g_pm, *g_pl, *g_pacc;
    cudaGetSymbolAddress((void**)&g_qkv,  s_qkv);
    cudaGetSymbolAddress((void**)&g_tmp,  s_tmp);
    cudaGetSymbolAddress((void**)&g_x1,   s_x1);
    cudaGetSymbolAddress((void**)&g_x2,   s_x2);
    cudaGetSymbolAddress((void**)&g_q,    s_q);
    cudaGetSymbolAddress((void**)&g_k,    s_k);
    cudaGetSymbolAddress((void**)&g_v,    s_v);
    cudaGetSymbolAddress((void**)&g_bias, s_bias);
    cudaGetSymbolAddress((void**)&g_part, s_part);
    cudaGetSymbolAddress((void**)&g_pm,   s_pm);
    cudaGetSymbolAddress((void**)&g_pl,   s_pl);
    cudaGetSymbolAddress((void**)&g_pacc, s_pacc);

    __half *hq, *hm, *h_siw, *h_sow, *h_qw, *h_kw, *h_vw, *h_ow,
           *h_fw1, *h_fw2, *hsa, *hca, *hx1, *hx2, *hffn;
    cudaGetSymbolAddress((void**)&hq,    h_queries);
    cudaGetSymbolAddress((void**)&hm,    h_memory);
    cudaGetSymbolAddress((void**)&h_siw, h_sa_in_w);
    cudaGetSymbolAddress((void**)&h_sow, h_sa_out_w);
    cudaGetSymbolAddress((void**)&h_qw,  h_q_w);
    cudaGetSymbolAddress((void**)&h_kw,  h_k_w);
    cudaGetSymbolAddress((void**)&h_vw,  h_v_w);
    cudaGetSymbolAddress((void**)&h_ow,  h_o_w);
    cudaGetSymbolAddress((void**)&h_fw1, h_ffn_w1);
    cudaGetSymbolAddress((void**)&h_fw2, h_ffn_w2);
    cudaGetSymbolAddress((void**)&hsa,   h_sa);
    cudaGetSymbolAddress((void**)&hca,   h_ca);
    cudaGetSymbolAddress((void**)&hx1,   h_x1);
    cudaGetSymbolAddress((void**)&hx2,   h_x2);
    cudaGetSymbolAddress((void**)&hffn,  h_ffn);

    static cudaStream_t st2 = nullptr, st3 = nullptr, st4 = nullptr;
    static cudaEvent_t ev0 = nullptr, ev2 = nullptr, ev3 = nullptr, ev4 = nullptr;
    if (st2 == nullptr) {
        cudaStreamCreateWithFlags(&st2, cudaStreamNonBlocking);
        cudaStreamCreateWithFlags(&st3, cudaStreamNonBlocking);
        cudaStreamCreateWithFlags(&st4, cudaStreamNonBlocking);
        cudaEventCreateWithFlags(&ev0, cudaEventDisableTiming);
        cudaEventCreateWithFlags(&ev2, cudaEventDisableTiming);
        cudaEventCreateWithFlags(&ev3, cudaEventDisableTiming);
        cudaEventCreateWithFlags(&ev4, cudaEventDisableTiming);
    }

    const int Mq = BB * QQ;   // 2400
    const int Mm = BB * LL;   // 8192
    const int NCOMB = BB * HH * QQ * (HD / 2);

    auto conv = [](const float* s, __half* d, int n, cudaStream_t st) {
        f2h_kernel<<<cdiv(n / 8, 256), 256, 0, st>>>(s, d, n);
    };

    // ---- fork ----
    cudaEventRecord(ev0, 0);
    cudaStreamWaitEvent(st2, ev0, 0);
    cudaStreamWaitEvent(st3, ev0, 0);
    cudaStreamWaitEvent(st4, ev0, 0);

    // st2: memory + KV weights conversion, then fused KV GEMM
    conv(memory, hm, Mm * DD, st2);
    conv(k_w, h_kw, DD * DD, st2);
    conv(v_w, h_vw, DD * DD, st2);
    gemm_f16_kernel<2><<<dim3(2 * DD / 64, cdiv(Mm, 128), 1), 256, 0, st2>>>(
        hm, h_kw, k_b, g_k, nullptr, Mm, DD, DD, 0, h_vw, v_b, g_v, nullptr);
    cudaEventRecord(ev2, st2);

    // st3: GASA bias
    gasa_bias_kernel<<<dim3(LL, BB), 128, 0, st3>>>(
        query_pos, memory_pos, dk_w1, dk_b1, dk_w2, dk_b2, beta, g_bias);
    cudaEventRecord(ev3, st3);

    // st4: remaining weights
    conv(sa_out_w, h_sow, DD * DD, st4);
    conv(q_w, h_qw, DD * DD, st4);
    conv(o_w, h_ow, DD * DD, st4);
    conv(ffn_w1, h_fw1, DFF * DD, st4);
    conv(ffn_w2, h_fw2, DD * DFF, st4);
    cudaEventRecord(ev4, st4);

    // ---- main chain ----
    conv(queries, hq, Mq * DD, 0);
    conv(sa_in_w, h_siw, 3 * DD * DD, 0);

    // 1) self-attn packed in-proj (fp32 out for attention)
    gemm_f16_kernel<2><<<dim3(3 * DD / 64, cdiv(Mq, 128), 1), 256>>>(
        hq, h_siw, sa_in_b, g_qkv, nullptr, Mq, 3 * DD, DD, 0);

    // 2) self-attention, split S=2 -> h_sa (fp16)
    {
        int S = 2, step = cdiv(QQ, S * 16) * 16;   // 304
        attn_mma_kernel<<<dim3(NQT * S, HH, BB), 128>>>(
            g_qkv, 3 * DD, g_qkv + DD, g_qkv + 2 * DD, 3 * DD,
            nullptr, QQ, S, step, g_pm, g_pl, g_pacc, 0);
        attn_combine_kernel<<<cdiv(NCOMB, 256), 256>>>(g_pm, g_pl, g_pacc, S, hsa);
    }

    cudaStreamWaitEvent(0, ev4, 0);

    // 3) SA out-proj + LN1 (x1 fp32 + fp16)
    gemm_f16_kernel<1><<<dim3(DD / 64, cdiv(Mq, 64), 1), 256>>>(
        hsa, h_sow, sa_out_b, g_tmp, nullptr, Mq, DD, DD, 0);
    ln_kernel<<<Mq / 8, 256>>>(queries, g_tmp, norm1_g, norm1_b, g_x1, hx1);

    // 4) Q projection (fp32 out for attention)
    gemm_f16_kernel<1><<<dim3(DD / 64, cdiv(Mq, 64), 1), 256>>>(
        hx1, h_qw, q_b, g_q, nullptr, Mq, DD, DD, 0);

    cudaStreamWaitEvent(0, ev2, 0);
    cudaStreamWaitEvent(0, ev3, 0);

    // 5) cross-attention, split S=4 -> h_ca (fp16)
    {
        int S = 4, step = cdiv(LL, S * 16) * 16;
        attn_mma_kernel<<<dim3(NQT * S, HH, BB), 128>>>(
            g_q, DD, g_k, g_v, DD, g_bias, LL, S, step, g_pm, g_pl, g_pacc, 1);
        attn_combine_kernel<<<cdiv(NCOMB, 256), 256>>>(g_pm, g_pl, g_pacc, S, hca);
    }

    // 6) O proj + LN2 (x2 fp32 + fp16)
    gemm_f16_kernel<1><<<dim3(DD / 64, cdiv(Mq, 64), 1), 256>>>(
        hca, h_ow, o_b, g_tmp, nullptr, Mq, DD, DD, 0);
    ln_kernel<<<Mq / 8, 256>>>(g_x1, g_tmp, norm2_g, norm2_b, g_x2, hx2);

    // 7) FFN1 (relu) -> fp16 only
    gemm_f16_kernel<2><<<dim3(DFF / 64, cdiv(Mq, 128), 1), 256>>>(
        hx2, h_fw1, ffn_b1, nullptr, hffn, Mq, DFF, DD, 1);

    // 8) FFN2 split-K=4 partials + fused combine in LN3 -> output
    gemm_f16_kernel<1><<<dim3(DD / 64, cdiv(Mq, 64), 4), 256>>>(
        hffn, h_fw2, ffn_b2, g_part, nullptr, Mq, DD, DFF, 0);
    ln_split_kernel<<<Mq / 8, 256>>>(g_x2, g_part, ffn_b2, norm3_g, norm3_b,
                                     (float*)d_out, 4);
}

// round 9
// speedup vs baseline: 1.2767x; 1.0439x over previous
#include <cuda_runtime.h>
#include <cuda_fp16.h>
#include <math.h>
#include <stdint.h>

// ---------------- problem constants ----------------
#define BB 4
#define QQ 600
#define LL 2048
#define DD 256
#define HH 8
#define HD 32
#define DFF 2048
#define KD 32
#define SCALE 0.17677669529663687f   // 32^-0.5
#define NQT 10                       // ceil(600/64) 64-query tiles

typedef unsigned long long u64;

// ---------------- helpers ----------------
__device__ __forceinline__ uint32_t f2tf32(float x) {
    uint32_t u; asm("cvt.rna.tf32.f32 %0, %1;" : "=r"(u) : "f"(x)); return u;
}
__device__ __forceinline__ void mma8(float c[4], uint32_t a0, uint32_t a1,
                                     uint32_t a2, uint32_t a3,
                                     uint32_t b0, uint32_t b1) {
    asm("mma.sync.aligned.m16n8k8.row.col.f32.tf32.tf32.f32 "
        "{%0,%1,%2,%3},{%4,%5,%6,%7},{%8,%9},{%0,%1,%2,%3};"
        : "+f"(c[0]), "+f"(c[1]), "+f"(c[2]), "+f"(c[3])
        : "r"(a0), "r"(a1), "r"(a2), "r"(a3), "r"(b0), "r"(b1));
}
__device__ __forceinline__ void mma16h(float c[4], uint32_t a0, uint32_t a1,
                                       uint32_t a2, uint32_t a3,
                                       uint32_t b0, uint32_t b1) {
    asm("mma.sync.aligned.m16n8k16.row.col.f32.f16.f16.f32 "
        "{%0,%1,%2,%3},{%4,%5,%6,%7},{%8,%9},{%0,%1,%2,%3};"
        : "+f"(c[0]), "+f"(c[1]), "+f"(c[2]), "+f"(c[3])
        : "r"(a0), "r"(a1), "r"(a2), "r"(a3), "r"(b0), "r"(b1));
}
__device__ __forceinline__ void ldsm4(uint32_t& r0, uint32_t& r1,
                                      uint32_t& r2, uint32_t& r3, uint32_t addr) {
    asm volatile("ldmatrix.sync.aligned.m8n8.x4.shared.b16 {%0,%1,%2,%3}, [%4];"
                 : "=r"(r0), "=r"(r1), "=r"(r2), "=r"(r3) : "r"(addr));
}
__device__ __forceinline__ void cp16(uint32_t dst, const void* src, int srcsize) {
    asm volatile("cp.async.ca.shared.global [%0], [%1], 16, %2;"
                 :: "r"(dst), "l"(src), "r"(srcsize));
}
__device__ __forceinline__ void cp_commit() {
    asm volatile("cp.async.commit_group;");
}
template<int N>
__device__ __forceinline__ void cp_wait() {
    asm volatile("cp.async.wait_group %0;" :: "n"(N));
}

// ---------------- scratch (device globals) ----------------
__device__ float s_qkv [BB*QQ*3*DD];
__device__ float s_x1  [BB*QQ*DD];
__device__ float s_x2  [BB*QQ*DD];
__device__ float s_q   [BB*QQ*DD];
__device__ float s_k   [BB*LL*DD];
__device__ float s_v   [BB*LL*DD];
__device__ float s_bias[BB*LL*QQ];
__device__ float s_part[4*BB*QQ*DD];
__device__ float s_pm  [BB*HH*8*QQ];
__device__ float s_pl  [BB*HH*8*QQ];
__device__ float s_pacc[BB*HH*8*QQ*HD];
// fp16 copies
__device__ __half h_queries[BB*QQ*DD];
__device__ __half h_memory [BB*LL*DD];
__device__ __half h_sa_in_w[3*DD*DD];
__device__ __half h_sa_out_w[DD*DD];
__device__ __half h_q_w[DD*DD];
__device__ __half h_k_w[DD*DD];
__device__ __half h_v_w[DD*DD];
__device__ __half h_o_w[DD*DD];
__device__ __half h_ffn_w1[DFF*DD];
__device__ __half h_ffn_w2[DD*DFF];
__device__ __half h_sa [BB*QQ*DD];
__device__ __half h_ca [BB*QQ*DD];
__device__ __half h_x1 [BB*QQ*DD];
__device__ __half h_x2 [BB*QQ*DD];
__device__ __half h_ffn[BB*QQ*DFF];

// ---------------- fp32 -> fp16 convert (8 elts/thread) ----------------
__global__ __launch_bounds__(256) void f2h_kernel(
    const float* __restrict__ src, __half* __restrict__ dst, int n)
{
    int i = (blockIdx.x * 256 + threadIdx.x) * 8;
    if (i >= n) return;
    float4 x0 = *reinterpret_cast<const float4*>(src + i);
    float4 x1 = *reinterpret_cast<const float4*>(src + i + 4);
    __half2 h0 = __floats2half2_rn(x0.x, x0.y);
    __half2 h1 = __floats2half2_rn(x0.z, x0.w);
    __half2 h2 = __floats2half2_rn(x1.x, x1.y);
    __half2 h3 = __floats2half2_rn(x1.z, x1.w);
    uint4 u;
    u.x = *reinterpret_cast<uint32_t*>(&h0);
    u.y = *reinterpret_cast<uint32_t*>(&h1);
    u.z = *reinterpret_cast<uint32_t*>(&h2);
    u.w = *reinterpret_cast<uint32_t*>(&h3);
    *reinterpret_cast<uint4*>(dst + i) = u;
}

// ---------------- FP16 tensor-core GEMM (cp.async + ldmatrix) -------------
#define KP 24      // halves per smem row (48B pitch, 16B segs conflict-free)
#define NST 3

template<int MF>
__global__ __launch_bounds__(256) void gemm_f16_kernel(
    const __half* __restrict__ A, const __half* __restrict__ W,
    const float* __restrict__ bias, float* C, __half* Ch,
    int M, int N, int K, int relu,
    const __half* __restrict__ W2 = nullptr,
    const float* __restrict__ bias2 = nullptr,
    float* C2 = nullptr, __half* C2h = nullptr)
{
    __shared__ __align__(16) __half As[NST][64 * MF][KP];
    __shared__ __align__(16) __half Ws[NST][64][KP];

    const int tid = threadIdx.x;
    const int lane = tid & 31;
    const int w = tid >> 5;
    const int wm = w & 3;
    const int wn = w >> 2;
    const int g = lane >> 2;
    const int t = lane & 3;

    int bx = blockIdx.x;
    const int nblk = N / 64;
    if (W2 != nullptr && bx >= nblk) {
        bx -= nblk;
        W = W2; bias = bias2; C = C2; Ch = C2h;
    }

    const int m0 = blockIdx.y * (64 * MF);
    const int n0 = bx * 64;

    const int nsplit = gridDim.z;
    const int Klen = K / nsplit;
    const int kstart = blockIdx.z * Klen;
    float* Cout = (C && nsplit > 1) ? (C + (size_t)blockIdx.z * M * N) : C;

    const uint32_t as_base = (uint32_t)__cvta_generic_to_shared(&As[0][0][0]);
    const uint32_t ws_base = (uint32_t)__cvta_generic_to_shared(&Ws[0][0][0]);

    float acc[MF][4][4];
    #pragma unroll
    for (int i = 0; i < MF; i++)
        #pragma unroll
        for (int j = 0; j < 4; j++)
            #pragma unroll
            for (int e = 0; e < 4; e++) acc[i][j][e] = 0.f;

    const int m_warp = wm * (16 * MF);
    const int n_warp = wn * 32;
    const int nIter = Klen / 16;

    // ldmatrix lane addressing
    const int lr8 = lane & 7;
    const int lb1 = (lane >> 3) & 1;
    const int lb2 = (lane >> 4) & 1;
    uint32_t aAddr[MF];
    #pragma unroll
    for (int mi = 0; mi < MF; mi++) {
        int row = m_warp + mi * 16 + lr8 + lb1 * 8;
        int koff = lb2 * 8;
        aAddr[mi] = as_base + (row * KP + koff) * 2;
    }
    uint32_t bAddr[2];
    #pragma unroll
    for (int p = 0; p < 2; p++) {
        int row = n_warp + p * 16 + lb2 * 8 + lr8;
        int koff = lb1 * 8;
        bAddr[p] = ws_base + (row * KP + koff) * 2;
    }
    const uint32_t aStride = (64 * MF) * KP * 2;
    const uint32_t bStride = 64 * KP * 2;

    auto load_stage = [&](int st, int it) {
        const int kg = kstart + it * 16;
        if (MF == 2) {
            int r = tid >> 1, kc = (tid & 1) * 8;
            int arow = m0 + r;
            uint32_t dst = as_base + ((st * 128 + r) * KP + kc) * 2;
            cp16(dst, A + (size_t)arow * K + kg + kc, (arow < M) ? 16 : 0);
            if (tid < 128) {
                int wr = tid >> 1, wkc = (tid & 1) * 8;
                uint32_t d2 = ws_base + ((st * 64 + wr) * KP + wkc) * 2;
                cp16(d2, W + (size_t)(n0 + wr) * K + kg + wkc, 16);
            }
        } else {
            if (tid < 128) {
                int r = tid >> 1, kc = (tid & 1) * 8;
                int arow = m0 + r;
                uint32_t dst = as_base + ((st * 64 + r) * KP + kc) * 2;
                cp16(dst, A + (size_t)arow * K + kg + kc, (arow < M) ? 16 : 0);
            } else {
                int r = (tid - 128) >> 1, kc = (tid & 1) * 8;
                uint32_t dst = ws_base + ((st * 64 + r) * KP + kc) * 2;
                cp16(dst, W + (size_t)(n0 + r) * K + kg + kc, 16);
            }
        }
        cp_commit();
    };

    load_stage(0, 0);
    load_stage(1, 1);

    for (int it = 0; it < nIter; it++) {
        cp_wait<NST - 2>();
        __syncthreads();
        if (it + NST - 1 < nIter) load_stage((it + NST - 1) % NST, it + NST - 1);
        else cp_commit();

        const int st = it % NST;
        uint32_t b0[4], b1[4];
        ldsm4(b0[0], b1[0], b0[1], b1[1], bAddr[0] + st * bStride);
        ldsm4(b0[2], b1[2], b0[3], b1[3], bAddr[1] + st * bStride);
        #pragma unroll
        for (int mi = 0; mi < MF; mi++) {
            uint32_t a0, a1, a2, a3;
            ldsm4(a0, a1, a2, a3, aAddr[mi] + st * aStride);
            #pragma unroll
            for (int ni = 0; ni < 4; ni++)
                mma16h(acc[mi][ni], a0, a1, a2, a3, b0[ni], b1[ni]);
        }
    }

    #pragma unroll
    for (int mi = 0; mi < MF; mi++) {
        #pragma unroll
        for (int ni = 0; ni < 4; ni++) {
            int col = n0 + n_warp + ni * 8 + 2 * t;
            float bz0 = 0.f, bz1 = 0.f;
            if (nsplit == 1) { bz0 = bias[col]; bz1 = bias[col + 1]; }
            int r0 = m0 + m_warp + mi * 16 + g;
            int r1 = r0 + 8;
            float v0 = acc[mi][ni][0] + bz0, v1 = acc[mi][ni][1] + bz1;
            float v2 = acc[mi][ni][2] + bz0, v3 = acc[mi][ni][3] + bz1;
            if (relu) {
                v0 = fmaxf(v0, 0.f); v1 = fmaxf(v1, 0.f);
                v2 = fmaxf(v2, 0.f); v3 = fmaxf(v3, 0.f);
            }
            if (Cout) {
                if (r0 < M) *reinterpret_cast<float2*>(Cout + (size_t)r0 * N + col) = make_float2(v0, v1);
                if (r1 < M) *reinterpret_cast<float2*>(Cout + (size_t)r1 * N + col) = make_float2(v2, v3);
            }
            if (Ch) {
                if (r0 < M) {
                    __half2 hv = __floats2half2_rn(v0, v1);
                    *reinterpret_cast<uint32_t*>(Ch + (size_t)r0 * N + col) =
                        *reinterpret_cast<uint32_t*>(&hv);
                }
                if (r1 < M) {
                    __half2 hv = __floats2half2_rn(v2, v3);
                    *reinterpret_cast<uint32_t*>(Ch + (size_t)r1 * N + col) =
                        *reinterpret_cast<uint32_t*>(&hv);
                }
            }
        }
    }
}

// ---------------- warp-per-row LayerNorm core ----------------
__device__ __forceinline__ void lnw_finish(
    float v[8], int lane, const float* g, const float* bt,
    float* out, __half* outh, size_t row)
{
    float s1 = 0.f, s2 = 0.f;
    #pragma unroll
    for (int i = 0; i < 8; i++) { s1 += v[i]; s2 += v[i] * v[i]; }
    #pragma unroll
    for (int o = 16; o > 0; o >>= 1) {
        s1 += __shfl_xor_sync(0xffffffffu, s1, o);
        s2 += __shfl_xor_sync(0xffffffffu, s2, o);
    }
    float mean = s1 * (1.f / DD);
    float var = s2 * (1.f / DD) - mean * mean;
    float rstd = rsqrtf(var + 1e-5f);
    int c0 = lane * 8;
    float r[8];
    #pragma unroll
    for (int i = 0; i < 8; i++)
        r[i] = (v[i] - mean) * rstd * g[c0 + i] + bt[c0 + i];
    if (out) {
        *reinterpret_cast<float4*>(out + row * DD + c0) = make_float4(r[0], r[1], r[2], r[3]);
        *reinterpret_cast<float4*>(out + row * DD + c0 + 4) = make_float4(r[4], r[5], r[6], r[7]);
    }
    if (outh) {
        __half2 h0 = __floats2half2_rn(r[0], r[1]);
        __half2 h1 = __floats2half2_rn(r[2], r[3]);
        __half2 h2 = __floats2half2_rn(r[4], r[5]);
        __half2 h3 = __floats2half2_rn(r[6], r[7]);
        uint4 u;
        u.x = *reinterpret_cast<uint32_t*>(&h0);
        u.y = *reinterpret_cast<uint32_t*>(&h1);
        u.z = *reinterpret_cast<uint32_t*>(&h2);
        u.w = *reinterpret_cast<uint32_t*>(&h3);
        *reinterpret_cast<uint4*>(outh + row * DD + c0) = u;
    }
}

// LN over (X + sum_s parts[s] + fbias) -> out (fp32) / outh (fp16, optional)
__global__ __launch_bounds__(256) void ln_split_kernel(
    const float* __restrict__ X, const float* __restrict__ parts,
    const float* __restrict__ fbias,
    const float* __restrict__ g, const float* __restrict__ bt,
    float* out, __half* outh, int nsplit)
{
    const int lane = threadIdx.x & 31;
    const size_t row = blockIdx.x * 8 + (threadIdx.x >> 5);
    const size_t stride = (size_t)BB * QQ * DD;
    int c0 = lane * 8;
    float v[8];
    float4 x0 = *reinterpret_cast<const float4*>(X + row * DD + c0);
    float4 x1 = *reinterpret_cast<const float4*>(X + row * DD + c0 + 4);
    float4 f0 = *reinterpret_cast<const float4*>(fbias + c0);
    float4 f1 = *reinterpret_cast<const float4*>(fbias + c0 + 4);
    v[0] = x0.x + f0.x; v[1] = x0.y + f0.y; v[2] = x0.z + f0.z; v[3] = x0.w + f0.w;
    v[4] = x1.x + f1.x; v[5] = x1.y + f1.y; v[6] = x1.z + f1.z; v[7] = x1.w + f1.w;
    for (int s = 0; s < nsplit; s++) {
        float4 p0 = *reinterpret_cast<const float4*>(parts + s * stride + row * DD + c0);
        float4 p1 = *reinterpret_cast<const float4*>(parts + s * stride + row * DD + c0 + 4);
        v[0] += p0.x; v[1] += p0.y; v[2] += p0.z; v[3] += p0.w;
        v[4] += p1.x; v[5] += p1.y; v[6] += p1.z; v[7] += p1.w;
    }
    lnw_finish(v, lane, g, bt, out, outh, row);
}

// ---------------- GASA geometric bias: block per (b,l) ----------------
__global__ __launch_bounds__(128) void gasa_bias_kernel(
    const float* __restrict__ qpos, const float* __restrict__ mpos,
    const float* __restrict__ w1, const float* __restrict__ b1,
    const float* __restrict__ w2, const float* __restrict__ b2,
    const float* __restrict__ betap, float* __restrict__ biasT)
{
    const int l = blockIdx.x;
    const int b = blockIdx.y;
    const int tid = threadIdx.x;

    __shared__ float sw1[KD], sb1[KD], sw2[KD], smp[3], sb2, sbeta;
    if (tid < KD) {
        sw1[tid] = w1[tid];
        sb1[tid] = b1[tid];
        sw2[tid] = w2[tid];
    }
    if (tid < 3) smp[tid] = mpos[((size_t)b * LL + l) * 3 + tid];
    if (tid == 3) sb2 = b2[0];
    if (tid == 4) sbeta = betap[0];
    __syncthreads();

    const float mx = smp[0], my = smp[1], mz = smp[2];
    const float bb2 = sb2, bet = sbeta;
    float* orow = biasT + ((size_t)b * LL + l) * QQ;

    for (int q = tid; q < QQ; q += 128) {
        const float* qp = qpos + ((size_t)b * QQ + q) * 3;
        float dx = qp[0] - mx, dy = qp[1] - my, dz = qp[2] - mz;
        float dist = sqrtf(fmaxf(dx * dx + dy * dy + dz * dz, 0.f));
        float s = 0.f;
        #pragma unroll
        for (int k = 0; k < KD; k++) {
            float h = fmaxf(dist * sw1[k] + sb1[k], 0.f);
            s += h * sw2[k];
        }
        s += bb2;
        s = fminf(fmaxf(s, -10.f), 0.f);
        orow[q] = s * bet;
    }
}

// ---------------- tensor-core flash attention partials ----------------
__global__ __launch_bounds__(128) void attn_mma_kernel(
    const float* __restrict__ Qp, int qstride,
    const float* __restrict__ Kp, const float* __restrict__ Vp, int kvstride,
    const float* __restrict__ biasT, int Lk, int S, int step,
    float* __restrict__ pm, float* __restrict__ pl, float* __restrict__ pacc,
    int useBias)
{
    const int b = blockIdx.z, h = blockIdx.y;
    const int sp = blockIdx.x / NQT;
    const int qt = blockIdx.x % NQT;
    const int tid = threadIdx.x;
    const int lane = tid & 31;
    const int warp = tid >> 5;
    const int g = lane >> 2;
    const int t = lane & 3;

    const int q0 = qt * 64 + warp * 16;
    const int qg  = q0 + g;
    const int qg8 = q0 + g + 8;
    const int qgc  = min(qg, QQ - 1);
    const int qg8c = min(qg8, QQ - 1);

    const int ls = sp * step;
    const int le = min(ls + step, Lk);

    uint32_t qa[4][4];
    {
        const float* q0p = Qp + ((size_t)(b * QQ + qgc)) * qstride + h * HD;
        const float* q1p = Qp + ((size_t)(b * QQ + qg8c)) * qstride + h * HD;
        #pragma unroll
        for (int ks = 0; ks < 4; ks++) {
            qa[ks][0] = f2tf32(q0p[ks * 8 + t] * SCALE);
            qa[ks][1] = f2tf32(q1p[ks * 8 + t] * SCALE);
            qa[ks][2] = f2tf32(q0p[ks * 8 + t + 4] * SCALE);
            qa[ks][3] = f2tf32(q1p[ks * 8 + t + 4] * SCALE);
        }
    }

    __shared__ uint32_t Ks[16][36];
    __shared__ uint32_t Vt[HD][17];
    __shared__ float    Bsm[16][68];

    float oacc[4][4];
    #pragma unroll
    for (int i = 0; i < 4; i++)
        #pragma unroll
        for (int j = 0; j < 4; j++) oacc[i][j] = 0.f;
    float om0 = -INFINITY, om1 = -INFINITY;
    float ol0 = 0.f, ol1 = 0.f;

    const int key_l = tid >> 3;
    const int d0 = (tid & 7) * 4;
    const int bq0 = (tid & 7) * 8;
    const bool qtail = (qt == NQT - 1);

    float4 kreg, vreg, breg0, breg1;

    auto prefetch = [&](int l0) {
        int grow = b * Lk + min(l0 + key_l, Lk - 1);
        kreg = *reinterpret_cast<const float4*>(
            Kp + (size_t)grow * kvstride + h * HD + d0);
        vreg = *reinterpret_cast<const float4*>(
            Vp + (size_t)grow * kvstride + h * HD + d0);
        if (useBias) {
            const float* brow = biasT + ((size_t)(b * Lk + l0 + key_l)) * QQ
                                + qt * 64 + bq0;
            if (!qtail) {
                breg0 = *reinterpret_cast<const float4*>(brow);
                breg1 = *reinterpret_cast<const float4*>(brow + 4);
            } else {
                int qb = qt * 64 + bq0;
                float e[8];
                #pragma unroll
                for (int i = 0; i < 8; i++)
                    e[i] = (qb + i < QQ) ? brow[i] : 0.f;
                breg0 = make_float4(e[0], e[1], e[2], e[3]);
                breg1 = make_float4(e[4], e[5], e[6], e[7]);
            }
        }
    };

    prefetch(ls);

    for (int l0 = ls; l0 < le; l0 += 16) {
        __syncthreads();
        {
            uint4 ku = make_uint4(f2tf32(kreg.x), f2tf32(kreg.y),
                                  f2tf32(kreg.z), f2tf32(kreg.w));
            *reinterpret_cast<uint4*>(&Ks[key_l][d0]) = ku;
            Vt[d0 + 0][key_l] = f2tf32(vreg.x);
            Vt[d0 + 1][key_l] = f2tf32(vreg.y);
            Vt[d0 + 2][key_l] = f2tf32(vreg.z);
            Vt[d0 + 3][key_l] = f2tf32(vreg.w);
            if (useBias) {
                *reinterpret_cast<float4*>(&Bsm[key_l][bq0]) = breg0;
                *reinterpret_cast<float4*>(&Bsm[key_l][bq0 + 4]) = breg1;
            }
        }
        if (l0 + 16 < le) prefetch(l0 + 16);
        __syncthreads();

        float sc[2][4];
        #pragma unroll
        for (int nf = 0; nf < 2; nf++) {
            sc[nf][0] = sc[nf][1] = sc[nf][2] = sc[nf][3] = 0.f;
            #pragma unroll
            for (int ks = 0; ks < 4; ks++) {
                uint32_t b0 = Ks[nf * 8 + g][ks * 8 + t];
                uint32_t b1 = Ks[nf * 8 + g][ks * 8 + t + 4];
                mma8(sc[nf], qa[ks][0], qa[ks][1], qa[ks][2], qa[ks][3], b0, b1);
            }
        }

        #pragma unroll
        for (int nf = 0; nf < 2; nf++) {
            if (useBias) {
                int brow = nf * 8 + 2 * t;
                int c0 = warp * 16 + g;
                sc[nf][0] += Bsm[brow][c0];
                sc[nf][1] += Bsm[brow + 1][c0];
                sc[nf][2] += Bsm[brow][c0 + 8];
                sc[nf][3] += Bsm[brow + 1][c0 + 8];
            }
            int kc = l0 + nf * 8 + 2 * t;
            if (kc >= le)     { sc[nf][0] = -1e30f; sc[nf][2] = -1e30f; }
            if (kc + 1 >= le) { sc[nf][1] = -1e30f; sc[nf][3] = -1e30f; }
        }

        float mx0 = fmaxf(fmaxf(sc[0][0], sc[0][1]), fmaxf(sc[1][0], sc[1][1]));
        float mx1 = fmaxf(fmaxf(sc[0][2], sc[0][3]), fmaxf(sc[1][2], sc[1][3]));
        mx0 = fmaxf(mx0, __shfl_xor_sync(0xffffffffu, mx0, 1));
        mx0 = fmaxf(mx0, __shfl_xor_sync(0xffffffffu, mx0, 2));
        mx1 = fmaxf(mx1, __shfl_xor_sync(0xffffffffu, mx1, 1));
        mx1 = fmaxf(mx1, __shfl_xor_sync(0xffffffffu, mx1, 2));

        float nm0 = fmaxf(om0, mx0), nm1 = fmaxf(om1, mx1);
        float cr0 = __expf(om0 - nm0), cr1 = __expf(om1 - nm1);
        om0 = nm0; om1 = nm1;
        ol0 *= cr0; ol1 *= cr1;
        #pragma unroll
        for (int nd = 0; nd < 4; nd++) {
            oacc[nd][0] *= cr0; oacc[nd][1] *= cr0;
            oacc[nd][2] *= cr1; oacc[nd][3] *= cr1;
        }

        #pragma unroll
        for (int nf = 0; nf < 2; nf++) {
            sc[nf][0] = __expf(sc[nf][0] - nm0);
            sc[nf][1] = __expf(sc[nf][1] - nm0);
            sc[nf][2] = __expf(sc[nf][2] - nm1);
            sc[nf][3] = __expf(sc[nf][3] - nm1);
            ol0 += sc[nf][0] + sc[nf][1];
            ol1 += sc[nf][2] + sc[nf][3];
        }

        #pragma unroll
        for (int ks = 0; ks < 2; ks++) {
            int src0 = t >> 1, src1 = (t >> 1) + 2;
            float v0 = __shfl_sync(0xffffffffu, sc[ks][0], src0, 4);
            float v1 = __shfl_sync(0xffffffffu, sc[ks][1], src0, 4);
            float v2 = __shfl_sync(0xffffffffu, sc[ks][2], src0, 4);
            float v3 = __shfl_sync(0xffffffffu, sc[ks][3], src0, 4);
            float w0 = __shfl_sync(0xffffffffu, sc[ks][0], src1, 4);
            float w1 = __shfl_sync(0xffffffffu, sc[ks][1], src1, 4);
            float w2 = __shfl_sync(0xffffffffu, sc[ks][2], src1, 4);
            float w3 = __shfl_sync(0xffffffffu, sc[ks][3], src1, 4);
            bool odd = (t & 1);
            uint32_t pa0 = f2tf32(odd ? v1 : v0);
            uint32_t pa1 = f2tf32(odd ? v3 : v2);
            uint32_t pa2 = f2tf32(odd ? w1 : w0);
            uint32_t pa3 = f2tf32(odd ? w3 : w2);
            #pragma unroll
            for (int nd = 0; nd < 4; nd++) {
                uint32_t b0 = Vt[nd * 8 + g][ks * 8 + t];
                uint32_t b1 = Vt[nd * 8 + g][ks * 8 + t + 4];
                mma8(oacc[nd], pa0, pa1, pa2, pa3, b0, b1);
            }
        }
    }

    ol0 += __shfl_xor_sync(0xffffffffu, ol0, 1);
    ol0 += __shfl_xor_sync(0xffffffffu, ol0, 2);
    ol1 += __shfl_xor_sync(0xffffffffu, ol1, 1);
    ol1 += __shfl_xor_sync(0xffffffffu, ol1, 2);

    size_t pbase = ((size_t)((b * HH + h) * S + sp)) * QQ;
    if (qg < QQ) {
        if (t == 0) { pm[pbase + qg] = om0; pl[pbase + qg] = ol0; }
        float* ap = pacc + (pbase + qg) * HD;
        #pragma unroll
        for (int nd = 0; nd < 4; nd++)
            *reinterpret_cast<float2*>(ap + nd * 8 + 2 * t) =
                make_float2(oacc[nd][0], oacc[nd][1]);
    }
    if (qg8 < QQ) {
        if (t == 0) { pm[pbase + qg8] = om1; pl[pbase + qg8] = ol1; }
        float* ap = pacc + (pbase + qg8) * HD;
        #pragma unroll
        for (int nd = 0; nd < 4; nd++)
            *reinterpret_cast<float2*>(ap + nd * 8 + 2 * t) =
                make_float2(oacc[nd][2], oacc[nd][3]);
    }
}

// ---------------- split combine (writes fp16 for GEMM consumption) --------
__global__ __launch_bounds__(256) void attn_combine_kernel(
    const float* __restrict__ pm, const float* __restrict__ pl,
    const float* __restrict__ pacc, int S, __half* __restrict__ out)
{
    int tt = blockIdx.x * 256 + threadIdx.x;
    if (tt >= BB * HH * QQ * (HD / 2)) return;
    int dp = tt & (HD / 2 - 1);
    int idx = tt >> 4;
    int q = idx % QQ;
    int bh = idx / QQ;
    int b = bh / HH, h = bh % HH;

    float mg = -INFINITY;
    for (int s = 0; s < S; s++)
        mg = fmaxf(mg, pm[((size_t)bh * S + s) * QQ + q]);
    float Lsum = 0.f;
    float olo = 0.f, ohi = 0.f;
    for (int s = 0; s < S; s++) {
        size_t pidx = ((size_t)bh * S + s) * QQ + q;
        float w = __expf(pm[pidx] - mg);
        Lsum += pl[pidx] * w;
        float2 a = *reinterpret_cast<const float2*>(pacc + pidx * HD + 2 * dp);
        olo += w * a.x; ohi += w * a.y;
    }
    float inv = 1.f / Lsum;
    __half2 hv = __floats2half2_rn(olo * inv, ohi * inv);
    *reinterpret_cast<uint32_t*>(
        out + ((size_t)(b * QQ + q)) * DD + h * HD + 2 * dp) =
        *reinterpret_cast<uint32_t*>(&hv);
}

// ---------------- host launcher ----------------
static inline int cdiv(int a, int b) { return (a + b - 1) / b; }

extern "C" void kernel_launch(void* const* d_in, const int* in_sizes, int n_in,
                              void* d_out, int out_size)
{
    const float* queries   = (const float*)d_in[0];
    const float* memory    = (const float*)d_in[1];
    const float* memory_pos= (const float*)d_in[2];
    const float* query_pos = (const float*)d_in[3];
    const float* sa_in_w   = (const float*)d_in[4];
    const float* sa_in_b   = (const float*)d_in[5];
    const float* sa_out_w  = (const float*)d_in[6];
    const float* sa_out_b  = (const float*)d_in[7];
    const float* norm1_g   = (const float*)d_in[8];
    const float* norm1_b   = (const float*)d_in[9];
    const float* q_w       = (const float*)d_in[10];
    const float* q_b       = (const float*)d_in[11];
    const float* k_w       = (const float*)d_in[12];
    const float* k_b       = (const float*)d_in[13];
    const float* v_w       = (const float*)d_in[14];
    const float* v_b       = (const float*)d_in[15];
    const float* o_w       = (const float*)d_in[16];
    const float* o_b       = (const float*)d_in[17];
    const float* norm2_g   = (const float*)d_in[18];
    const float* norm2_b   = (const float*)d_in[19];
    const float* beta      = (const float*)d_in[20];
    const float* dk_w1     = (const float*)d_in[21];
    const float* dk_b1     = (const float*)d_in[22];
    const float* dk_w2     = (const float*)d_in[23];
    const float* dk_b2     = (const float*)d_in[24];
    const float* ffn_w1    = (const float*)d_in[25];
    const float* ffn_b1    = (const float*)d_in[26];
    const float* ffn_w2    = (const float*)d_in[27];
    const float* ffn_b2    = (const float*)d_in[28];
    const float* norm3_g   = (const float*)d_in[29];
    const float* norm3_b   = (const float*)d_in[30];

    float *g_qkv, *g_x1, *g_x2, *g_q, *g_k, *g_v, *g_bias,
          *g_part, *g_pm, *g_pl, *g_pacc;
    cudaGetSymbolAddress((void**)&g_qkv,  s_qkv);
    cudaGetSymbolAddress((void**)&g_x1,   s_x1);
    cudaGetSymbolAddress((void**)&g_x2,   s_x2);
    cudaGetSymbolAddress((void**)&g_q,    s_q);
    cudaGetSymbolAddress((void**)&g_k,    s_k);
    cudaGetSymbolAddress((void**)&g_v,    s_v);
    cudaGetSymbolAddress((void**)&g_bias, s_bias);
    cudaGetSymbolAddress((void**)&g_part, s_part);
    cudaGetSymbolAddress((void**)&g_pm,   s_pm);
    cudaGetSymbolAddress((void**)&g_pl,   s_pl);
    cudaGetSymbolAddress((void**)&g_pacc, s_pacc);

    __half *hq, *hm, *h_siw, *h_sow, *h_qw, *h_kw, *h_vw, *h_ow,
           *h_fw1, *h_fw2, *hsa, *hca, *hx1, *hx2, *hffn;
    cudaGetSymbolAddress((void**)&hq,    h_queries);
    cudaGetSymbolAddress((void**)&hm,    h_memory);
    cudaGetSymbolAddress((void**)&h_siw, h_sa_in_w);
    cudaGetSymbolAddress((void**)&h_sow, h_sa_out_w);
    cudaGetSymbolAddress((void**)&h_qw,  h_q_w);
    cudaGetSymbolAddress((void**)&h_kw,  h_k_w);
    cudaGetSymbolAddress((void**)&h_vw,  h_v_w);
    cudaGetSymbolAddress((void**)&h_ow,  h_o_w);
    cudaGetSymbolAddress((void**)&h_fw1, h_ffn_w1);
    cudaGetSymbolAddress((void**)&h_fw2, h_ffn_w2);
    cudaGetSymbolAddress((void**)&hsa,   h_sa);
    cudaGetSymbolAddress((void**)&hca,   h_ca);
    cudaGetSymbolAddress((void**)&hx1,   h_x1);
    cudaGetSymbolAddress((void**)&hx2,   h_x2);
    cudaGetSymbolAddress((void**)&hffn,  h_ffn);

    static cudaStream_t st2 = nullptr, st3 = nullptr, st4 = nullptr;
    static cudaEvent_t ev0 = nullptr, ev2 = nullptr, ev3 = nullptr,
                       ev4 = nullptr, ev5 = nullptr;
    if (st2 == nullptr) {
        cudaStreamCreateWithFlags(&st2, cudaStreamNonBlocking);
        cudaStreamCreateWithFlags(&st3, cudaStreamNonBlocking);
        cudaStreamCreateWithFlags(&st4, cudaStreamNonBlocking);
        cudaEventCreateWithFlags(&ev0, cudaEventDisableTiming);
        cudaEventCreateWithFlags(&ev2, cudaEventDisableTiming);
        cudaEventCreateWithFlags(&ev3, cudaEventDisableTiming);
        cudaEventCreateWithFlags(&ev4, cudaEventDisableTiming);
        cudaEventCreateWithFlags(&ev5, cudaEventDisableTiming);
    }

    const int Mq = BB * QQ;   // 2400
    const int Mm = BB * LL;   // 8192
    const int NCOMB = BB * HH * QQ * (HD / 2);

    auto conv = [](const float* s, __half* d, int n, cudaStream_t st) {
        f2h_kernel<<<cdiv(n / 8, 256), 256, 0, st>>>(s, d, n);
    };

    // ---- fork ----
    cudaEventRecord(ev0, 0);
    cudaStreamWaitEvent(st2, ev0, 0);
    cudaStreamWaitEvent(st3, ev0, 0);
    cudaStreamWaitEvent(st4, ev0, 0);

    // st2: memory + KV weights conversion, then fused KV GEMM
    conv(memory, hm, Mm * DD, st2);
    conv(k_w, h_kw, DD * DD, st2);
    conv(v_w, h_vw, DD * DD, st2);
    gemm_f16_kernel<2><<<dim3(2 * DD / 64, cdiv(Mm, 128), 1), 256, 0, st2>>>(
        hm, h_kw, k_b, g_k, nullptr, Mm, DD, DD, 0, h_vw, v_b, g_v, nullptr);
    cudaEventRecord(ev2, st2);

    // st3: GASA bias
    gasa_bias_kernel<<<dim3(LL, BB), 128, 0, st3>>>(
        query_pos, memory_pos, dk_w1, dk_b1, dk_w2, dk_b2, beta, g_bias);
    cudaEventRecord(ev3, st3);

    // st4: sa_in_w first (critical for GEMM1), then remaining weights
    conv(sa_in_w, h_siw, 3 * DD * DD, st4);
    cudaEventRecord(ev5, st4);
    conv(sa_out_w, h_sow, DD * DD, st4);
    conv(q_w, h_qw, DD * DD, st4);
    conv(o_w, h_ow, DD * DD, st4);
    conv(ffn_w1, h_fw1, DFF * DD, st4);
    conv(ffn_w2, h_fw2, DD * DFF, st4);
    cudaEventRecord(ev4, st4);

    // ---- main chain ----
    conv(queries, hq, Mq * DD, 0);
    cudaStreamWaitEvent(0, ev5, 0);

    // 1) self-attn packed in-proj (fp32 out for attention)
    gemm_f16_kernel<2><<<dim3(3 * DD / 64, cdiv(Mq, 128), 1), 256>>>(
        hq, h_siw, sa_in_b, g_qkv, nullptr, Mq, 3 * DD, DD, 0);

    // 2) self-attention, split S=2 -> h_sa (fp16)
    {
        int S = 2, step = cdiv(QQ, S * 16) * 16;   // 304
        attn_mma_kernel<<<dim3(NQT * S, HH, BB), 128>>>(
            g_qkv, 3 * DD, g_qkv + DD, g_qkv + 2 * DD, 3 * DD,
            nullptr, QQ, S, step, g_pm, g_pl, g_pacc, 0);
        attn_combine_kernel<<<cdiv(NCOMB, 256), 256>>>(g_pm, g_pl, g_pacc, S, hsa);
    }

    cudaStreamWaitEvent(0, ev4, 0);

    // 3) SA out-proj split-K=2 + LN1 (x1 fp32 + fp16)
    gemm_f16_kernel<1><<<dim3(DD / 64, cdiv(Mq, 64), 2), 256>>>(
        hsa, h_sow, sa_out_b, g_part, nullptr, Mq, DD, DD, 0);
    ln_split_kernel<<<Mq / 8, 256>>>(queries, g_part, sa_out_b,
                                     norm1_g, norm1_b, g_x1, hx1, 2);

    // 4) Q projection (fp32 out for attention)
    gemm_f16_kernel<1><<<dim3(DD / 64, cdiv(Mq, 64), 1), 256>>>(
        hx1, h_qw, q_b, g_q, nullptr, Mq, DD, DD, 0);

    cudaStreamWaitEvent(0, ev2, 0);
    cudaStreamWaitEvent(0, ev3, 0);

    // 5) cross-attention, split S=4 -> h_ca (fp16)
    {
        int S = 4, step = cdiv(LL, S * 16) * 16;
        attn_mma_kernel<<<dim3(NQT * S, HH, BB), 128>>>(
            g_q, DD, g_k, g_v, DD, g_bias, LL, S, step, g_pm, g_pl, g_pacc, 1);
        attn_combine_kernel<<<cdiv(NCOMB, 256), 256>>>(g_pm, g_pl, g_pacc, S, hca);
    }

    // 6) O proj split-K=2 + LN2 (x2 fp32 + fp16)
    gemm_f16_kernel<1><<<dim3(DD / 64, cdiv(Mq, 64), 2), 256>>>(
        hca, h_ow, o_b, g_part, nullptr, Mq, DD, DD, 0);
    ln_split_kernel<<<Mq / 8, 256>>>(g_x1, g_part, o_b,
                                     norm2_g, norm2_b, g_x2, hx2, 2);

    // 7) FFN1 (relu) -> fp16 only
    gemm_f16_kernel<2><<<dim3(DFF / 64, cdiv(Mq, 128), 1), 256>>>(
        hx2, h_fw1, ffn_b1, nullptr, hffn, Mq, DFF, DD, 1);

    // 8) FFN2 split-K=4 partials + fused combine in LN3 -> output
    gemm_f16_kernel<1><<<dim3(DD / 64, cdiv(Mq, 64), 4), 256>>>(
        hffn, h_fw2, ffn_b2, g_part, nullptr, Mq, DD, DFF, 0);
    ln_split_kernel<<<Mq / 8, 256>>>(g_x2, g_part, ffn_b2,
                                     norm3_g, norm3_b, (float*)d_out, nullptr, 4);
}